// round 2
// baseline (speedup 1.0000x reference)
#include <cuda_runtime.h>
#include <math.h>

// Problem constants
#define Bq 32
#define Tq 12
#define Nq 512
#define Cq 2
#define Hq 64
#define Kq 3
#define Pq 66            // C + H
#define NBC (Bq*Pq)      // 2112 columns of Combined
#define KP  (Kq*Pq)      // 198
#define OUTG (2*Hq)      // 128

// Scratch state (device globals; no allocations allowed)
__device__ float g_h[Bq*Nq*Hq];      // current hidden state [b][n][h]
__device__ float g_comb[Nq*NBC];     // Combined matrix [j][b*P+p]
__device__ float g_sup[Bq*Nq*KP];    // GCN support [b][n][k][p]
__device__ float g_z[Bq*Nq*Hq];      // gate z [b][n][h]

// ---------------------------------------------------------------------------
// init: h = init_h, and seed the h-columns of Combined
// ---------------------------------------------------------------------------
__global__ void init_kernel(const float* __restrict__ init_h) {
    int idx = blockIdx.x * blockDim.x + threadIdx.x;  // over B*N*H
    if (idx >= Bq*Nq*Hq) return;
    float v = init_h[idx];
    g_h[idx] = v;
    int hid = idx % Hq;
    int row = idx / Hq;          // b*N + n
    int b = row / Nq;
    int n = row % Nq;
    g_comb[n*NBC + b*Pq + Cq + hid] = v;
}

// ---------------------------------------------------------------------------
// set_x: write x_t into the x-columns of Combined
// ---------------------------------------------------------------------------
__global__ void set_x_kernel(const float* __restrict__ x_seq, int t) {
    int idx = blockIdx.x * blockDim.x + threadIdx.x;  // over B*N*C
    if (idx >= Bq*Nq*Cq) return;
    int p = idx % Cq;
    int rest = idx / Cq;
    int n = rest % Nq;
    int b = rest / Nq;
    g_comb[n*NBC + b*Pq + p] = x_seq[((b*Tq + t)*Nq + n)*Cq + p];
}

// ---------------------------------------------------------------------------
// GEMM1: Sup[b,n,k,p] = sum_j G[k,n,j] * Comb[j, b*P+p]
// A = G[k] (512x512), B = Comb (512x2112).  Tile 128x64, K-tile 16.
// 256 threads, 8x4 microtile per thread.
// ---------------------------------------------------------------------------
#define BM 128
#define BN 64
#define BKT 16

__global__ __launch_bounds__(256) void gemm1_kernel(const float* __restrict__ G) {
    const int k  = blockIdx.z;
    const int bm = blockIdx.y;   // 0..3
    const int bn = blockIdx.x;   // 0..32
    const float* A  = G + k*Nq*Nq + bm*BM*Nq;
    const float* Bp = g_comb + bn*BN;

    __shared__ float As[BKT][BM + 4];   // padded: conflict-free transpose stores
    __shared__ float Bs[BKT][BN];

    const int tid  = threadIdx.x;
    const int tidm = tid >> 4;   // 0..15 -> rows tidm*8..+7
    const int tidn = tid & 15;   // 0..15 -> cols tidn*4..+3

    float acc[8][4];
    #pragma unroll
    for (int i = 0; i < 8; i++)
        #pragma unroll
        for (int j = 0; j < 4; j++)
            acc[i][j] = 0.0f;

    for (int kt = 0; kt < Nq; kt += BKT) {
        // Load A tile (128x16) = 512 float4, 2 per thread; store transposed.
        #pragma unroll
        for (int l = 0; l < 2; l++) {
            int q   = tid + l*256;
            int row = q >> 2;        // 0..127
            int c4  = q & 3;         // 0..3
            float4 v = *(const float4*)(A + row*Nq + kt + c4*4);
            As[c4*4+0][row] = v.x;
            As[c4*4+1][row] = v.y;
            As[c4*4+2][row] = v.z;
            As[c4*4+3][row] = v.w;
        }
        // Load B tile (16x64) = 256 float4, 1 per thread.
        {
            int row = tid >> 4;      // 0..15
            int c4  = tid & 15;      // 0..15
            float4 v = *(const float4*)(Bp + (kt + row)*NBC + c4*4);
            *(float4*)&Bs[row][c4*4] = v;
        }
        __syncthreads();

        #pragma unroll
        for (int kk = 0; kk < BKT; kk++) {
            float a[8], bb[4];
            #pragma unroll
            for (int i = 0; i < 8; i++) a[i] = As[kk][tidm*8 + i];
            #pragma unroll
            for (int j = 0; j < 4; j++) bb[j] = Bs[kk][tidn*4 + j];
            #pragma unroll
            for (int i = 0; i < 8; i++)
                #pragma unroll
                for (int j = 0; j < 4; j++)
                    acc[i][j] = fmaf(a[i], bb[j], acc[i][j]);
        }
        __syncthreads();
    }

    // Scatter into Sup [b][n][k][p]
    #pragma unroll
    for (int j = 0; j < 4; j++) {
        int col = bn*BN + tidn*4 + j;
        int b = col / Pq;
        int p = col - b*Pq;
        #pragma unroll
        for (int i = 0; i < 8; i++) {
            int n = bm*BM + tidm*8 + i;
            g_sup[((b*Nq + n)*Kq + k)*Pq + p] = acc[i][j];
        }
    }
}

// ---------------------------------------------------------------------------
// GEMM2 + fused epilogues.
// Rows (b,n) of Sup (198 wide) @ W (198 x OUT) + bias, then:
//   GATE:   zr = sigmoid; o<H -> store z; o>=H -> Comb h-col = r * h
//   UPDATE: hc = tanh; h = (1-z)h + z*hc; write h, Comb h-col, (out if last)
// Block: OUT threads, ROWS=16 rows per block.
// ---------------------------------------------------------------------------
template<int OUT, bool GATE>
__global__ void gemm2_kernel(const float* __restrict__ W,
                             const float* __restrict__ bias,
                             float* __restrict__ out, int is_last) {
    __shared__ float sh[16][KP + 2];
    const int row0 = blockIdx.x * 16;
    const int o = threadIdx.x;

    for (int idx = o; idx < 16*KP; idx += OUT) {
        int r  = idx / KP;
        int kk = idx - r*KP;
        sh[r][kk] = g_sup[(row0 + r)*KP + kk];
    }
    __syncthreads();

    float acc[16];
    const float bo = bias[o];
    #pragma unroll
    for (int r = 0; r < 16; r++) acc[r] = bo;

    #pragma unroll 6
    for (int kk = 0; kk < KP; kk++) {
        float w = W[kk*OUT + o];
        #pragma unroll
        for (int r = 0; r < 16; r++)
            acc[r] = fmaf(sh[r][kk], w, acc[r]);
    }

    #pragma unroll
    for (int r = 0; r < 16; r++) {
        int row = row0 + r;       // b*N + n
        int b = row >> 9;         // N = 512
        int n = row & (Nq - 1);
        if (GATE) {
            float zv = 1.0f / (1.0f + __expf(-acc[r]));
            if (o < Hq) {
                g_z[row*Hq + o] = zv;
            } else {
                int hid = o - Hq;
                float hv = g_h[row*Hq + hid];
                g_comb[n*NBC + b*Pq + Cq + hid] = zv * hv;   // candidate h-part
            }
        } else {
            float hc   = tanhf(acc[r]);
            float zv   = g_z[row*Hq + o];
            float hold = g_h[row*Hq + o];
            float hnew = (1.0f - zv)*hold + zv*hc;
            g_h[row*Hq + o] = hnew;
            g_comb[n*NBC + b*Pq + Cq + o] = hnew;            // next-step h-part
            if (is_last) out[row*Hq + o] = hnew;
        }
    }
}

// ---------------------------------------------------------------------------
// kernel_launch
// Inputs (metadata order): G, x_seq, init_h, W_gate, b_gate, W_update, b_update
// ---------------------------------------------------------------------------
extern "C" void kernel_launch(void* const* d_in, const int* in_sizes, int n_in,
                              void* d_out, int out_size) {
    const float* G        = (const float*)d_in[0];
    const float* x_seq    = (const float*)d_in[1];
    const float* init_h   = (const float*)d_in[2];
    const float* W_gate   = (const float*)d_in[3];
    const float* b_gate   = (const float*)d_in[4];
    const float* W_update = (const float*)d_in[5];
    const float* b_update = (const float*)d_in[6];
    float* out = (float*)d_out;

    init_kernel<<<(Bq*Nq*Hq + 255)/256, 256>>>(init_h);

    dim3 g1(NBC/BN, Nq/BM, Kq);   // (33, 4, 3)
    for (int t = 0; t < Tq; t++) {
        set_x_kernel<<<(Bq*Nq*Cq + 255)/256, 256>>>(x_seq, t);
        gemm1_kernel<<<g1, 256>>>(G);
        gemm2_kernel<OUTG, true><<<Bq*Nq/16, OUTG>>>(W_gate, b_gate, out, 0);
        gemm1_kernel<<<g1, 256>>>(G);
        gemm2_kernel<Hq, false><<<Bq*Nq/16, Hq>>>(W_update, b_update, out, t == Tq - 1);
    }
}

// round 5
// speedup vs baseline: 1.0176x; 1.0176x over previous
#include <cuda_runtime.h>
#include <math.h>

// Problem constants
#define Bq 32
#define Tq 12
#define Nq 512
#define Cq 2
#define Hq 64
#define Kq 3
#define Pq 66            // C + H
#define NBC (Bq*Pq)      // 2112 columns of Combined
#define KP  (Kq*Pq)      // 198
#define KSTRIDE 200      // sup row stride (float4-aligned: 800 B)
#define KLOOP 208        // k-loop bound (13 tiles of 16)
#define OUTG (2*Hq)      // 128
#define NROWS (Bq*Nq)    // 16384

// Scratch state (device globals; no allocations allowed)
__device__ float g_h[Bq*Nq*Hq];            // current hidden state [b][n][h]
__device__ float g_comb[Nq*NBC];           // Combined matrix [j][b*P+p]
__device__ float g_sup[NROWS*KSTRIDE + 16];// GCN support [b*N+n][k*P+p] (stride 200, +16 overread pad)
__device__ float g_z[Bq*Nq*Hq];            // gate z [b][n][h]

// ---------------------------------------------------------------------------
// init: h = init_h, and seed the h-columns of Combined
// ---------------------------------------------------------------------------
__global__ void init_kernel(const float* __restrict__ init_h) {
    int idx = blockIdx.x * blockDim.x + threadIdx.x;  // over B*N*H
    if (idx >= Bq*Nq*Hq) return;
    float v = init_h[idx];
    g_h[idx] = v;
    int hid = idx % Hq;
    int row = idx / Hq;          // b*N + n
    int b = row / Nq;
    int n = row % Nq;
    g_comb[n*NBC + b*Pq + Cq + hid] = v;
}

// ---------------------------------------------------------------------------
// set_x: write x_t into the x-columns of Combined
// ---------------------------------------------------------------------------
__global__ void set_x_kernel(const float* __restrict__ x_seq, int t) {
    int idx = blockIdx.x * blockDim.x + threadIdx.x;  // over B*N*C
    if (idx >= Bq*Nq*Cq) return;
    int p = idx % Cq;
    int rest = idx / Cq;
    int n = rest % Nq;
    int b = rest / Nq;
    g_comb[n*NBC + b*Pq + p] = x_seq[((b*Tq + t)*Nq + n)*Cq + p];
}

// ---------------------------------------------------------------------------
// GEMM1: Sup[b,n,k,p] = sum_j G[k,n,j] * Comb[j, b*P+p]
// A = G[k] (512x512), B = Comb (512x2112).  Tile 128x64, K-tile 16.
// ---------------------------------------------------------------------------
#define BM 128
#define BN 64
#define BKT 16

__global__ __launch_bounds__(256) void gemm1_kernel(const float* __restrict__ G) {
    const int k  = blockIdx.z;
    const int bm = blockIdx.y;   // 0..3
    const int bn = blockIdx.x;   // 0..32
    const float* A  = G + k*Nq*Nq + bm*BM*Nq;
    const float* Bp = g_comb + bn*BN;

    __shared__ float As[BKT][BM + 4];   // padded: conflict-free transpose stores
    __shared__ float Bs[BKT][BN];

    const int tid  = threadIdx.x;
    const int tidm = tid >> 4;   // 0..15 -> rows tidm*8..+7
    const int tidn = tid & 15;   // 0..15 -> cols tidn*4..+3

    float acc[8][4];
    #pragma unroll
    for (int i = 0; i < 8; i++)
        #pragma unroll
        for (int j = 0; j < 4; j++)
            acc[i][j] = 0.0f;

    for (int kt = 0; kt < Nq; kt += BKT) {
        #pragma unroll
        for (int l = 0; l < 2; l++) {
            int q   = tid + l*256;
            int row = q >> 2;        // 0..127
            int c4  = q & 3;         // 0..3
            float4 v = *(const float4*)(A + row*Nq + kt + c4*4);
            As[c4*4+0][row] = v.x;
            As[c4*4+1][row] = v.y;
            As[c4*4+2][row] = v.z;
            As[c4*4+3][row] = v.w;
        }
        {
            int row = tid >> 4;      // 0..15
            int c4  = tid & 15;      // 0..15
            float4 v = *(const float4*)(Bp + (kt + row)*NBC + c4*4);
            *(float4*)&Bs[row][c4*4] = v;
        }
        __syncthreads();

        #pragma unroll
        for (int kk = 0; kk < BKT; kk++) {
            float a[8], bb[4];
            #pragma unroll
            for (int i = 0; i < 8; i++) a[i] = As[kk][tidm*8 + i];
            #pragma unroll
            for (int j = 0; j < 4; j++) bb[j] = Bs[kk][tidn*4 + j];
            #pragma unroll
            for (int i = 0; i < 8; i++)
                #pragma unroll
                for (int j = 0; j < 4; j++)
                    acc[i][j] = fmaf(a[i], bb[j], acc[i][j]);
        }
        __syncthreads();
    }

    // Scatter into Sup [b*N+n][k*P+p] (row stride KSTRIDE)
    #pragma unroll
    for (int j = 0; j < 4; j++) {
        int col = bn*BN + tidn*4 + j;
        int b = col / Pq;
        int p = col - b*Pq;
        #pragma unroll
        for (int i = 0; i < 8; i++) {
            int n = bm*BM + tidm*8 + i;
            g_sup[(b*Nq + n)*KSTRIDE + k*Pq + p] = acc[i][j];
        }
    }
}

// ---------------------------------------------------------------------------
// GEMM2 (register-tiled) + fused epilogues.
// A = Sup (16384 rows, stride 200), B = W (KP x OUT, from harness input).
// K-loop runs 13 tiles to 208; B rows >= KP are zeroed by predicate, so any
// garbage in A columns 198..207 multiplies zero.
// grid = (OUT/64, 16384/128), 256 threads, 8x4 microtile.
//   GATE:   zr = sigmoid; o<H -> store z; o>=H -> Comb h-col = r * h
//   UPDATE: hc = tanh; h = (1-z)h + z*hc; write h, Comb h-col, (out if last)
// ---------------------------------------------------------------------------
template<int OUT, bool GATE>
__global__ __launch_bounds__(256) void gemm2t_kernel(const float* __restrict__ W,
                                                     const float* __restrict__ bias,
                                                     float* __restrict__ out, int is_last) {
    const int bn = blockIdx.x;         // 0..OUT/64-1
    const int bm = blockIdx.y;         // 0..127
    const float* A  = g_sup + bm*BM*KSTRIDE;
    const float* Bp = W + bn*BN;

    __shared__ float As[BKT][BM + 4];
    __shared__ float Bs[BKT][BN];

    const int tid  = threadIdx.x;
    const int tidm = tid >> 4;
    const int tidn = tid & 15;

    float acc[8][4];
    #pragma unroll
    for (int j = 0; j < 4; j++) {
        float bv = bias[bn*BN + tidn*4 + j];
        #pragma unroll
        for (int i = 0; i < 8; i++) acc[i][j] = bv;
    }

    for (int kt = 0; kt < KLOOP; kt += BKT) {
        #pragma unroll
        for (int l = 0; l < 2; l++) {
            int q   = tid + l*256;
            int row = q >> 2;        // 0..127
            int c4  = q & 3;         // 0..3
            float4 v = *(const float4*)(A + row*KSTRIDE + kt + c4*4);
            As[c4*4+0][row] = v.x;
            As[c4*4+1][row] = v.y;
            As[c4*4+2][row] = v.z;
            As[c4*4+3][row] = v.w;
        }
        {
            int row = tid >> 4;      // 0..15
            int c4  = tid & 15;      // 0..15
            float4 v = make_float4(0.f, 0.f, 0.f, 0.f);
            if (kt + row < KP)
                v = *(const float4*)(Bp + (kt + row)*OUT + c4*4);
            *(float4*)&Bs[row][c4*4] = v;
        }
        __syncthreads();

        #pragma unroll
        for (int kk = 0; kk < BKT; kk++) {
            float a[8], bb[4];
            #pragma unroll
            for (int i = 0; i < 8; i++) a[i] = As[kk][tidm*8 + i];
            #pragma unroll
            for (int j = 0; j < 4; j++) bb[j] = Bs[kk][tidn*4 + j];
            #pragma unroll
            for (int i = 0; i < 8; i++)
                #pragma unroll
                for (int j = 0; j < 4; j++)
                    acc[i][j] = fmaf(a[i], bb[j], acc[i][j]);
        }
        __syncthreads();
    }

    // Fused epilogue
    #pragma unroll
    for (int i = 0; i < 8; i++) {
        int row = bm*BM + tidm*8 + i;   // b*N + n
        int b = row >> 9;               // N = 512
        int n = row & (Nq - 1);
        #pragma unroll
        for (int j = 0; j < 4; j++) {
            int o = bn*BN + tidn*4 + j;
            if (GATE) {
                float zv = 1.0f / (1.0f + __expf(-acc[i][j]));
                if (o < Hq) {
                    g_z[row*Hq + o] = zv;
                } else {
                    int hid = o - Hq;
                    float hv = g_h[row*Hq + hid];
                    g_comb[n*NBC + b*Pq + Cq + hid] = zv * hv;   // candidate h-part
                }
            } else {
                float hc   = tanhf(acc[i][j]);
                float zv   = g_z[row*Hq + o];
                float hold = g_h[row*Hq + o];
                float hnew = (1.0f - zv)*hold + zv*hc;
                g_h[row*Hq + o] = hnew;
                g_comb[n*NBC + b*Pq + Cq + o] = hnew;            // next-step h-part
                if (is_last) out[row*Hq + o] = hnew;
            }
        }
    }
}

// ---------------------------------------------------------------------------
// kernel_launch
// Inputs (metadata order): G, x_seq, init_h, W_gate, b_gate, W_update, b_update
// ---------------------------------------------------------------------------
extern "C" void kernel_launch(void* const* d_in, const int* in_sizes, int n_in,
                              void* d_out, int out_size) {
    const float* G        = (const float*)d_in[0];
    const float* x_seq    = (const float*)d_in[1];
    const float* init_h   = (const float*)d_in[2];
    const float* W_gate   = (const float*)d_in[3];
    const float* b_gate   = (const float*)d_in[4];
    const float* W_update = (const float*)d_in[5];
    const float* b_update = (const float*)d_in[6];
    float* out = (float*)d_out;

    init_kernel<<<(Bq*Nq*Hq + 255)/256, 256>>>(init_h);

    dim3 g1(NBC/BN, Nq/BM, Kq);          // (33, 4, 3)
    dim3 g2g(OUTG/BN, NROWS/BM);         // (2, 128)
    dim3 g2u(Hq/BN,  NROWS/BM);          // (1, 128)
    for (int t = 0; t < Tq; t++) {
        set_x_kernel<<<(Bq*Nq*Cq + 255)/256, 256>>>(x_seq, t);
        gemm1_kernel<<<g1, 256>>>(G);
        gemm2t_kernel<OUTG, true><<<g2g, 256>>>(W_gate, b_gate, out, 0);
        gemm1_kernel<<<g1, 256>>>(G);
        gemm2t_kernel<Hq, false><<<g2u, 256>>>(W_update, b_update, out, t == Tq - 1);
    }
}

// round 7
// speedup vs baseline: 1.4724x; 1.4470x over previous
#include <cuda_runtime.h>
#include <cuda_bf16.h>
#include <cstdint>
#include <math.h>

// Problem constants
#define Bq 32
#define Tq 12
#define Nq 512
#define Cq 2
#define Hq 64
#define Kq 3
#define Pq 66            // C + H
#define NCOLS (Bq*Pq)    // 2112 columns of Combined
#define KP  (Kq*Pq)      // 198
#define KSTRIDE 200      // sup row stride (float4-aligned)
#define KLOOP 208        // gemm2 k-loop bound (13 tiles of 16)
#define OUTG (2*Hq)      // 128
#define NROWS (Bq*Nq)    // 16384

// ---------------- device state (no allocations allowed) ----------------
__device__ float g_h[Bq*Nq*Hq];             // hidden state fp32 [b*N+n][h]
__device__ float g_sup[NROWS*KSTRIDE + 16]; // GCN support fp32 (stride 200)
__device__ float g_z[Bq*Nq*Hq];             // gate z
__device__ __nv_bfloat16 g_gHi[Kq*Nq*Nq];   // G split hi [k][n][j]
__device__ __nv_bfloat16 g_gLo[Kq*Nq*Nq];   // G split lo
__device__ __nv_bfloat16 g_ctHi[NCOLS*Nq];  // Combined^T hi [col][j]
__device__ __nv_bfloat16 g_ctLo[NCOLS*Nq];  // Combined^T lo

__device__ __forceinline__ void split_bf16(float v, __nv_bfloat16& hi, __nv_bfloat16& lo) {
    hi = __float2bfloat16(v);
    lo = __float2bfloat16(v - __bfloat162float(hi));
}

// ---------------- prep: split G into bf16 hi/lo ----------------
__global__ void prep_g_kernel(const float* __restrict__ G) {
    int idx = blockIdx.x * blockDim.x + threadIdx.x;
    if (idx >= Kq*Nq*Nq) return;
    __nv_bfloat16 hi, lo;
    split_bf16(G[idx], hi, lo);
    g_gHi[idx] = hi;
    g_gLo[idx] = lo;
}

// ---------------- init: h = init_h, seed combT h-rows ----------------
__global__ void init_kernel(const float* __restrict__ init_h) {
    int idx = blockIdx.x * blockDim.x + threadIdx.x;  // over B*N*H
    if (idx >= Bq*Nq*Hq) return;
    float v = init_h[idx];
    g_h[idx] = v;
    int hid = idx % Hq;
    int row = idx / Hq;          // b*N + n
    int b = row / Nq;
    int n = row % Nq;
    __nv_bfloat16 hi, lo;
    split_bf16(v, hi, lo);
    int ct = (b*Pq + Cq + hid)*Nq + n;
    g_ctHi[ct] = hi;
    g_ctLo[ct] = lo;
}

// ---------------- set_x: x_t into combT x-rows ----------------
__global__ void set_x_kernel(const float* __restrict__ x_seq, int t) {
    int idx = blockIdx.x * blockDim.x + threadIdx.x;  // over B*N*C
    if (idx >= Bq*Nq*Cq) return;
    int p = idx % Cq;
    int rest = idx / Cq;
    int n = rest % Nq;
    int b = rest / Nq;
    float v = x_seq[((b*Tq + t)*Nq + n)*Cq + p];
    __nv_bfloat16 hi, lo;
    split_bf16(v, hi, lo);
    int ct = (b*Pq + p)*Nq + n;
    g_ctHi[ct] = hi;
    g_ctLo[ct] = lo;
}

// ---------------------------------------------------------------------------
// GEMM1 via mma.sync (HMMA, base sm_100): Sup = G[k] @ Comb, split-bf16 3-pass.
// NT GEMM: A = G[k] rows m, contiguous k.  BT = combT rows n, contiguous k.
// CTA tile 128x96, K-chunk 32.  8 warps (4 in M x 2 in N), warp tile 32x48.
// grid (22, 4, 3).
// ---------------------------------------------------------------------------
#define SASTRIDE 40     // bf16 elements per smem row (80 B, ldmatrix conflict-free)

__device__ __forceinline__ void ldm_x4(uint32_t* r, uint32_t addr) {
    asm volatile("ldmatrix.sync.aligned.m8n8.x4.shared.b16 {%0,%1,%2,%3}, [%4];"
                 : "=r"(r[0]), "=r"(r[1]), "=r"(r[2]), "=r"(r[3]) : "r"(addr));
}
__device__ __forceinline__ void mma_bf16(float* c, const uint32_t* a, const uint32_t* b) {
    asm volatile("mma.sync.aligned.m16n8k16.row.col.f32.bf16.bf16.f32 "
                 "{%0,%1,%2,%3}, {%4,%5,%6,%7}, {%8,%9}, {%0,%1,%2,%3};"
                 : "+f"(c[0]), "+f"(c[1]), "+f"(c[2]), "+f"(c[3])
                 : "r"(a[0]), "r"(a[1]), "r"(a[2]), "r"(a[3]), "r"(b[0]), "r"(b[1]));
}
__device__ __forceinline__ uint32_t smem_u32(const void* p) {
    uint32_t a;
    asm("{ .reg .u64 t; cvta.to.shared.u64 t, %1; cvt.u32.u64 %0, t; }" : "=r"(a) : "l"(p));
    return a;
}

__global__ __launch_bounds__(256) void gemm1_mma_kernel() {
    const int kk = blockIdx.z;     // graph kernel 0..2
    const int bm = blockIdx.y;     // 0..3   (M band of 128)
    const int bn = blockIdx.x;     // 0..21  (N band of 96)
    const int tid  = threadIdx.x;
    const int wid  = tid >> 5;
    const int lane = tid & 31;
    const int wm = wid & 3;        // m offset 32*wm
    const int wn = wid >> 2;       // n offset 48*wn

    __shared__ __nv_bfloat16 sAhi[128*SASTRIDE];
    __shared__ __nv_bfloat16 sAlo[128*SASTRIDE];
    __shared__ __nv_bfloat16 sBhi[96*SASTRIDE];
    __shared__ __nv_bfloat16 sBlo[96*SASTRIDE];

    const __nv_bfloat16* Ahi0 = g_gHi + kk*Nq*Nq + bm*128*Nq;
    const __nv_bfloat16* Alo0 = g_gLo + kk*Nq*Nq + bm*128*Nq;
    const __nv_bfloat16* Bhi0 = g_ctHi + bn*96*Nq;
    const __nv_bfloat16* Blo0 = g_ctLo + bn*96*Nq;

    const uint32_t uAhi = smem_u32(sAhi);
    const uint32_t uAlo = smem_u32(sAlo);
    const uint32_t uBhi = smem_u32(sBhi);
    const uint32_t uBlo = smem_u32(sBlo);

    float acc[2][6][4];
    #pragma unroll
    for (int i = 0; i < 2; i++)
        #pragma unroll
        for (int j = 0; j < 6; j++)
            #pragma unroll
            for (int r = 0; r < 4; r++) acc[i][j][r] = 0.0f;

    // ldmatrix per-lane row/byte offsets (within a tile), in bytes
    // A (x4 over m16k16): row = lane&15 (+mf*16 + wm*32), kbyte = (lane>>4)*16
    const uint32_t aRow  = (uint32_t)(lane & 15);
    const uint32_t aKoff = (uint32_t)((lane >> 4) * 16);
    // B (x4 over n16k16): row = (lane&7) + ((lane>>4)<<3), kbyte = ((lane>>3)&1)*16
    const uint32_t bRow  = (uint32_t)((lane & 7) + ((lane >> 4) << 3));
    const uint32_t bKoff = (uint32_t)(((lane >> 3) & 1) * 16);

    for (int kt = 0; kt < Nq; kt += 32) {
        __syncthreads();
        // Stage A (128 rows x 32 bf16 = 4 uint4/row) and B (96 rows)
        #pragma unroll
        for (int l = 0; l < 2; l++) {
            int idx = tid + l*256;           // 0..511
            int r = idx >> 2, q = idx & 3;
            *(uint4*)(sAhi + r*SASTRIDE + q*8) = *(const uint4*)(Ahi0 + r*Nq + kt + q*8);
            *(uint4*)(sAlo + r*SASTRIDE + q*8) = *(const uint4*)(Alo0 + r*Nq + kt + q*8);
        }
        {
            int idx = tid;                   // 0..255 of 384
            int r = idx >> 2, q = idx & 3;
            *(uint4*)(sBhi + r*SASTRIDE + q*8) = *(const uint4*)(Bhi0 + r*Nq + kt + q*8);
            *(uint4*)(sBlo + r*SASTRIDE + q*8) = *(const uint4*)(Blo0 + r*Nq + kt + q*8);
            if (tid < 128) {
                idx = tid + 256;
                r = idx >> 2; q = idx & 3;
                *(uint4*)(sBhi + r*SASTRIDE + q*8) = *(const uint4*)(Bhi0 + r*Nq + kt + q*8);
                *(uint4*)(sBlo + r*SASTRIDE + q*8) = *(const uint4*)(Blo0 + r*Nq + kt + q*8);
            }
        }
        __syncthreads();

        #pragma unroll
        for (int ks = 0; ks < 2; ks++) {
            const uint32_t kByte = (uint32_t)(ks * 32);

            uint32_t fAhi[2][4], fAlo[2][4], fB[3][4];

            // Ahi, Bhi
            #pragma unroll
            for (int mf = 0; mf < 2; mf++)
                ldm_x4(fAhi[mf], uAhi + (wm*32 + mf*16 + aRow)*(SASTRIDE*2) + aKoff + kByte);
            #pragma unroll
            for (int q = 0; q < 3; q++)
                ldm_x4(fB[q], uBhi + (wn*48 + q*16 + bRow)*(SASTRIDE*2) + bKoff + kByte);
            #pragma unroll
            for (int mf = 0; mf < 2; mf++)
                #pragma unroll
                for (int q = 0; q < 3; q++) {
                    mma_bf16(acc[mf][2*q+0], fAhi[mf], &fB[q][0]);
                    mma_bf16(acc[mf][2*q+1], fAhi[mf], &fB[q][2]);
                }

            // Alo x Bhi
            #pragma unroll
            for (int mf = 0; mf < 2; mf++)
                ldm_x4(fAlo[mf], uAlo + (wm*32 + mf*16 + aRow)*(SASTRIDE*2) + aKoff + kByte);
            #pragma unroll
            for (int mf = 0; mf < 2; mf++)
                #pragma unroll
                for (int q = 0; q < 3; q++) {
                    mma_bf16(acc[mf][2*q+0], fAlo[mf], &fB[q][0]);
                    mma_bf16(acc[mf][2*q+1], fAlo[mf], &fB[q][2]);
                }

            // Ahi x Blo (reuse B regs)
            #pragma unroll
            for (int q = 0; q < 3; q++)
                ldm_x4(fB[q], uBlo + (wn*48 + q*16 + bRow)*(SASTRIDE*2) + bKoff + kByte);
            #pragma unroll
            for (int mf = 0; mf < 2; mf++)
                #pragma unroll
                for (int q = 0; q < 3; q++) {
                    mma_bf16(acc[mf][2*q+0], fAhi[mf], &fB[q][0]);
                    mma_bf16(acc[mf][2*q+1], fAhi[mf], &fB[q][2]);
                }
        }
    }

    // Epilogue: scatter accumulators to g_sup
    const int quad = lane >> 2;
    const int tq   = lane & 3;
    #pragma unroll
    for (int mf = 0; mf < 2; mf++) {
        #pragma unroll
        for (int nf = 0; nf < 6; nf++) {
            #pragma unroll
            for (int r = 0; r < 4; r++) {
                int m = bm*128 + wm*32 + mf*16 + ((r >> 1) << 3) + quad;  // graph node n
                int col = bn*96 + wn*48 + nf*8 + tq*2 + (r & 1);
                int b = col / Pq;
                int p = col - b*Pq;
                g_sup[(b*Nq + m)*KSTRIDE + kk*Pq + p] = acc[mf][nf][r];
            }
        }
    }
}

// ---------------------------------------------------------------------------
// GEMM2 (register-tiled SIMT) + fused epilogues (writes combT hi/lo splits).
// ---------------------------------------------------------------------------
#define BM 128
#define BN 64
#define BKT 16

template<int OUT, bool GATE>
__global__ __launch_bounds__(256) void gemm2t_kernel(const float* __restrict__ W,
                                                     const float* __restrict__ bias,
                                                     float* __restrict__ out, int is_last) {
    const int bn = blockIdx.x;
    const int bm = blockIdx.y;
    const float* A  = g_sup + bm*BM*KSTRIDE;
    const float* Bp = W + bn*BN;

    __shared__ float As[BKT][BM + 4];
    __shared__ float Bs[BKT][BN];

    const int tid  = threadIdx.x;
    const int tidm = tid >> 4;
    const int tidn = tid & 15;

    float acc[8][4];
    #pragma unroll
    for (int j = 0; j < 4; j++) {
        float bv = bias[bn*BN + tidn*4 + j];
        #pragma unroll
        for (int i = 0; i < 8; i++) acc[i][j] = bv;
    }

    for (int kt = 0; kt < KLOOP; kt += BKT) {
        #pragma unroll
        for (int l = 0; l < 2; l++) {
            int q   = tid + l*256;
            int row = q >> 2;
            int c4  = q & 3;
            float4 v = *(const float4*)(A + row*KSTRIDE + kt + c4*4);
            As[c4*4+0][row] = v.x;
            As[c4*4+1][row] = v.y;
            As[c4*4+2][row] = v.z;
            As[c4*4+3][row] = v.w;
        }
        {
            int row = tid >> 4;
            int c4  = tid & 15;
            float4 v = make_float4(0.f, 0.f, 0.f, 0.f);
            if (kt + row < KP)
                v = *(const float4*)(Bp + (kt + row)*OUT + c4*4);
            *(float4*)&Bs[row][c4*4] = v;
        }
        __syncthreads();

        #pragma unroll
        for (int kq = 0; kq < BKT; kq++) {
            float a[8], bb[4];
            #pragma unroll
            for (int i = 0; i < 8; i++) a[i] = As[kq][tidm*8 + i];
            #pragma unroll
            for (int j = 0; j < 4; j++) bb[j] = Bs[kq][tidn*4 + j];
            #pragma unroll
            for (int i = 0; i < 8; i++)
                #pragma unroll
                for (int j = 0; j < 4; j++)
                    acc[i][j] = fmaf(a[i], bb[j], acc[i][j]);
        }
        __syncthreads();
    }

    #pragma unroll
    for (int i = 0; i < 8; i++) {
        int row = bm*BM + tidm*8 + i;   // b*N + n
        int b = row >> 9;
        int n = row & (Nq - 1);
        #pragma unroll
        for (int j = 0; j < 4; j++) {
            int o = bn*BN + tidn*4 + j;
            if (GATE) {
                float zv = 1.0f / (1.0f + __expf(-acc[i][j]));
                if (o < Hq) {
                    g_z[row*Hq + o] = zv;
                } else {
                    int hid = o - Hq;
                    float rh = zv * g_h[row*Hq + hid];
                    __nv_bfloat16 hi, lo;
                    split_bf16(rh, hi, lo);
                    int ct = (b*Pq + Cq + hid)*Nq + n;
                    g_ctHi[ct] = hi;
                    g_ctLo[ct] = lo;
                }
            } else {
                float hc   = tanhf(acc[i][j]);
                float zv   = g_z[row*Hq + o];
                float hold = g_h[row*Hq + o];
                float hnew = (1.0f - zv)*hold + zv*hc;
                g_h[row*Hq + o] = hnew;
                __nv_bfloat16 hi, lo;
                split_bf16(hnew, hi, lo);
                int ct = (b*Pq + Cq + o)*Nq + n;
                g_ctHi[ct] = hi;
                g_ctLo[ct] = lo;
                if (is_last) out[row*Hq + o] = hnew;
            }
        }
    }
}

// ---------------------------------------------------------------------------
// kernel_launch
// Inputs: G, x_seq, init_h, W_gate, b_gate, W_update, b_update
// ---------------------------------------------------------------------------
extern "C" void kernel_launch(void* const* d_in, const int* in_sizes, int n_in,
                              void* d_out, int out_size) {
    const float* G        = (const float*)d_in[0];
    const float* x_seq    = (const float*)d_in[1];
    const float* init_h   = (const float*)d_in[2];
    const float* W_gate   = (const float*)d_in[3];
    const float* b_gate   = (const float*)d_in[4];
    const float* W_update = (const float*)d_in[5];
    const float* b_update = (const float*)d_in[6];
    float* out = (float*)d_out;

    prep_g_kernel<<<(Kq*Nq*Nq + 255)/256, 256>>>(G);
    init_kernel<<<(Bq*Nq*Hq + 255)/256, 256>>>(init_h);

    dim3 g1(NCOLS/96, Nq/128, Kq);       // (22, 4, 3)
    dim3 g2g(OUTG/BN, NROWS/BM);         // (2, 128)
    dim3 g2u(Hq/BN,  NROWS/BM);          // (1, 128)
    for (int t = 0; t < Tq; t++) {
        set_x_kernel<<<(Bq*Nq*Cq + 255)/256, 256>>>(x_seq, t);
        gemm1_mma_kernel<<<g1, 256>>>();
        gemm2t_kernel<OUTG, true><<<g2g, 256>>>(W_gate, b_gate, out, 0);
        gemm1_mma_kernel<<<g1, 256>>>();
        gemm2t_kernel<Hq, false><<<g2u, 256>>>(W_update, b_update, out, t == Tq - 1);
    }
}

// round 8
// speedup vs baseline: 1.5587x; 1.0587x over previous
#include <cuda_runtime.h>
#include <cuda_bf16.h>
#include <cstdint>
#include <math.h>

// Problem constants
#define Bq 32
#define Tq 12
#define Nq 512
#define Cq 2
#define Hq 64
#define Kq 3
#define Pq 66            // C + H
#define NCOLS (Bq*Pq)    // 2112 columns of Combined
#define KP  (Kq*Pq)      // 198
#define KSTRIDE 200      // sup row stride (float4-aligned)
#define KLOOP 208        // gemm2 k-loop bound (13 tiles of 16)
#define OUTG (2*Hq)      // 128
#define NROWS (Bq*Nq)    // 16384

// ---------------- device state (no allocations allowed) ----------------
__device__ float g_h[Bq*Nq*Hq];             // hidden state fp32 [b*N+n][h]
__device__ float g_sup[NROWS*KSTRIDE + 16]; // GCN support fp32 (stride 200)
__device__ float g_z[Bq*Nq*Hq];             // gate z
__device__ __nv_bfloat16 g_gHi[Kq*Nq*Nq];   // G split hi [k][n][j]
__device__ __nv_bfloat16 g_gLo[Kq*Nq*Nq];   // G split lo
__device__ __nv_bfloat16 g_ctHi[NCOLS*Nq];  // Combined^T hi [col][j]
__device__ __nv_bfloat16 g_ctLo[NCOLS*Nq];  // Combined^T lo

__device__ __forceinline__ void split_bf16(float v, __nv_bfloat16& hi, __nv_bfloat16& lo) {
    hi = __float2bfloat16(v);
    lo = __float2bfloat16(v - __bfloat162float(hi));
}

// ---------------- prep: split G into bf16 hi/lo ----------------
__global__ void prep_g_kernel(const float* __restrict__ G) {
    int idx = blockIdx.x * blockDim.x + threadIdx.x;
    if (idx >= Kq*Nq*Nq) return;
    __nv_bfloat16 hi, lo;
    split_bf16(G[idx], hi, lo);
    g_gHi[idx] = hi;
    g_gLo[idx] = lo;
}

// ---------------- init: h = init_h, seed combT h-rows ----------------
__global__ void init_kernel(const float* __restrict__ init_h) {
    int idx = blockIdx.x * blockDim.x + threadIdx.x;  // over B*N*H
    if (idx >= Bq*Nq*Hq) return;
    float v = init_h[idx];
    g_h[idx] = v;
    int hid = idx % Hq;
    int row = idx / Hq;          // b*N + n
    int b = row / Nq;
    int n = row % Nq;
    __nv_bfloat16 hi, lo;
    split_bf16(v, hi, lo);
    int ct = (b*Pq + Cq + hid)*Nq + n;
    g_ctHi[ct] = hi;
    g_ctLo[ct] = lo;
}

// ---------------- set_x: x_t into combT x-rows ----------------
__global__ void set_x_kernel(const float* __restrict__ x_seq, int t) {
    int idx = blockIdx.x * blockDim.x + threadIdx.x;  // over B*N*C
    if (idx >= Bq*Nq*Cq) return;
    int p = idx % Cq;
    int rest = idx / Cq;
    int n = rest % Nq;
    int b = rest / Nq;
    float v = x_seq[((b*Tq + t)*Nq + n)*Cq + p];
    __nv_bfloat16 hi, lo;
    split_bf16(v, hi, lo);
    int ct = (b*Pq + p)*Nq + n;
    g_ctHi[ct] = hi;
    g_ctLo[ct] = lo;
}

// ---------------------------------------------------------------------------
// GEMM1 via mma.sync, split-bf16 3-pass, cp.async double-buffered pipeline.
// NT GEMM: A = G[k] rows m, contiguous k.  BT = combT rows n, contiguous k.
// CTA tile 128x96, K-chunk 32.  8 warps (4 in M x 2 in N), warp tile 32x48.
// grid (22, 4, 3), 256 threads, dynamic smem = 2 stages x 35840 B.
// ---------------------------------------------------------------------------
#define SASTRIDE 40     // bf16 per smem row (80 B, ldmatrix conflict-free)
#define ROWB 80         // row bytes
#define OFF_AHI 0
#define OFF_ALO 10240
#define OFF_BHI 20480
#define OFF_BLO 28160
#define STGSZ   35840
#define SMEM_G1 (2*STGSZ)   // 71680 B

__device__ __forceinline__ void ldm_x4(uint32_t* r, uint32_t addr) {
    asm volatile("ldmatrix.sync.aligned.m8n8.x4.shared.b16 {%0,%1,%2,%3}, [%4];"
                 : "=r"(r[0]), "=r"(r[1]), "=r"(r[2]), "=r"(r[3]) : "r"(addr));
}
__device__ __forceinline__ void mma_bf16(float* c, const uint32_t* a, const uint32_t* b) {
    asm volatile("mma.sync.aligned.m16n8k16.row.col.f32.bf16.bf16.f32 "
                 "{%0,%1,%2,%3}, {%4,%5,%6,%7}, {%8,%9}, {%0,%1,%2,%3};"
                 : "+f"(c[0]), "+f"(c[1]), "+f"(c[2]), "+f"(c[3])
                 : "r"(a[0]), "r"(a[1]), "r"(a[2]), "r"(a[3]), "r"(b[0]), "r"(b[1]));
}
__device__ __forceinline__ uint32_t smem_u32(const void* p) {
    uint32_t a;
    asm("{ .reg .u64 t; cvta.to.shared.u64 t, %1; cvt.u32.u64 %0, t; }" : "=r"(a) : "l"(p));
    return a;
}
__device__ __forceinline__ void cp16(uint32_t dst, const void* src) {
    asm volatile("cp.async.cg.shared.global [%0], [%1], 16;" :: "r"(dst), "l"(src));
}
#define CP_COMMIT() asm volatile("cp.async.commit_group;" ::: "memory")
#define CP_WAIT1()  asm volatile("cp.async.wait_group 1;" ::: "memory")
#define CP_WAIT0()  asm volatile("cp.async.wait_group 0;" ::: "memory")

__global__ __launch_bounds__(256) void gemm1_mma_kernel() {
    extern __shared__ char smg[];
    const int kk = blockIdx.z;     // graph kernel 0..2
    const int bm = blockIdx.y;     // 0..3   (M band of 128)
    const int bn = blockIdx.x;     // 0..21  (N band of 96)
    const int tid  = threadIdx.x;
    const int wid  = tid >> 5;
    const int lane = tid & 31;
    const int wm = wid & 3;        // m offset 32*wm
    const int wn = wid >> 2;       // n offset 48*wn
    const uint32_t sm0 = smem_u32(smg);

    const __nv_bfloat16* Ahi0 = g_gHi + kk*Nq*Nq + bm*128*Nq;
    const __nv_bfloat16* Alo0 = g_gLo + kk*Nq*Nq + bm*128*Nq;
    const __nv_bfloat16* Bhi0 = g_ctHi + bn*96*Nq;
    const __nv_bfloat16* Blo0 = g_ctLo + bn*96*Nq;

    // Staging geometry (per thread): A uses idx=tid, tid+256; B uses idx=tid (+256 if tid<128)
    const int rA0 = tid >> 2,          qA0 = (tid & 3);
    const int rA1 = (tid + 256) >> 2,  qA1 = (tid & 3);
    const int rB0 = tid >> 2,          qB0 = (tid & 3);
    const int rB1 = (tid + 256) >> 2,  qB1 = (tid & 3);

    float acc[2][6][4];
    #pragma unroll
    for (int i = 0; i < 2; i++)
        #pragma unroll
        for (int j = 0; j < 6; j++)
            #pragma unroll
            for (int r = 0; r < 4; r++) acc[i][j][r] = 0.0f;

    // ldmatrix per-lane offsets (bytes, within a tile)
    const uint32_t aOff = (uint32_t)((lane & 15) * ROWB + (lane >> 4) * 16);
    const uint32_t bOff = (uint32_t)(((lane & 7) + ((lane >> 4) << 3)) * ROWB
                                     + (((lane >> 3) & 1) * 16));

    // ---- prefetch chunk 0 ----
    {
        const uint32_t base = sm0;
        cp16(base + OFF_AHI + rA0*ROWB + qA0*16, Ahi0 + rA0*Nq + qA0*8);
        cp16(base + OFF_ALO + rA0*ROWB + qA0*16, Alo0 + rA0*Nq + qA0*8);
        cp16(base + OFF_AHI + rA1*ROWB + qA1*16, Ahi0 + rA1*Nq + qA1*8);
        cp16(base + OFF_ALO + rA1*ROWB + qA1*16, Alo0 + rA1*Nq + qA1*8);
        cp16(base + OFF_BHI + rB0*ROWB + qB0*16, Bhi0 + rB0*Nq + qB0*8);
        cp16(base + OFF_BLO + rB0*ROWB + qB0*16, Blo0 + rB0*Nq + qB0*8);
        if (tid < 128) {
            cp16(base + OFF_BHI + rB1*ROWB + qB1*16, Bhi0 + rB1*Nq + qB1*8);
            cp16(base + OFF_BLO + rB1*ROWB + qB1*16, Blo0 + rB1*Nq + qB1*8);
        }
        CP_COMMIT();
    }

    for (int c = 0; c < 16; c++) {
        // ---- prefetch chunk c+1 into the other stage ----
        if (c < 15) {
            const uint32_t base = sm0 + ((c + 1) & 1) * STGSZ;
            const int kt = (c + 1) * 32;
            cp16(base + OFF_AHI + rA0*ROWB + qA0*16, Ahi0 + rA0*Nq + kt + qA0*8);
            cp16(base + OFF_ALO + rA0*ROWB + qA0*16, Alo0 + rA0*Nq + kt + qA0*8);
            cp16(base + OFF_AHI + rA1*ROWB + qA1*16, Ahi0 + rA1*Nq + kt + qA1*8);
            cp16(base + OFF_ALO + rA1*ROWB + qA1*16, Alo0 + rA1*Nq + kt + qA1*8);
            cp16(base + OFF_BHI + rB0*ROWB + qB0*16, Bhi0 + rB0*Nq + kt + qB0*8);
            cp16(base + OFF_BLO + rB0*ROWB + qB0*16, Blo0 + rB0*Nq + kt + qB0*8);
            if (tid < 128) {
                cp16(base + OFF_BHI + rB1*ROWB + qB1*16, Bhi0 + rB1*Nq + kt + qB1*8);
                cp16(base + OFF_BLO + rB1*ROWB + qB1*16, Blo0 + rB1*Nq + kt + qB1*8);
            }
            CP_COMMIT();
            CP_WAIT1();     // chunk c's group complete (c+1 may be in flight)
        } else {
            CP_WAIT0();
        }
        __syncthreads();

        // ---- compute on stage c&1 ----
        const uint32_t base = sm0 + (c & 1) * STGSZ;
        const uint32_t uAhi = base + OFF_AHI;
        const uint32_t uAlo = base + OFF_ALO;
        const uint32_t uBhi = base + OFF_BHI;
        const uint32_t uBlo = base + OFF_BLO;

        #pragma unroll
        for (int ks = 0; ks < 2; ks++) {
            const uint32_t kByte = (uint32_t)(ks * 32);

            uint32_t fAhi[2][4], fAlo[2][4], fB[3][4];

            // Ahi, Bhi
            #pragma unroll
            for (int mf = 0; mf < 2; mf++)
                ldm_x4(fAhi[mf], uAhi + (wm*32 + mf*16)*ROWB + aOff + kByte);
            #pragma unroll
            for (int q = 0; q < 3; q++)
                ldm_x4(fB[q], uBhi + (wn*48 + q*16)*ROWB + bOff + kByte);
            #pragma unroll
            for (int mf = 0; mf < 2; mf++)
                #pragma unroll
                for (int q = 0; q < 3; q++) {
                    mma_bf16(acc[mf][2*q+0], fAhi[mf], &fB[q][0]);
                    mma_bf16(acc[mf][2*q+1], fAhi[mf], &fB[q][2]);
                }

            // Alo x Bhi
            #pragma unroll
            for (int mf = 0; mf < 2; mf++)
                ldm_x4(fAlo[mf], uAlo + (wm*32 + mf*16)*ROWB + aOff + kByte);
            #pragma unroll
            for (int mf = 0; mf < 2; mf++)
                #pragma unroll
                for (int q = 0; q < 3; q++) {
                    mma_bf16(acc[mf][2*q+0], fAlo[mf], &fB[q][0]);
                    mma_bf16(acc[mf][2*q+1], fAlo[mf], &fB[q][2]);
                }

            // Ahi x Blo (reuse B regs)
            #pragma unroll
            for (int q = 0; q < 3; q++)
                ldm_x4(fB[q], uBlo + (wn*48 + q*16)*ROWB + bOff + kByte);
            #pragma unroll
            for (int mf = 0; mf < 2; mf++)
                #pragma unroll
                for (int q = 0; q < 3; q++) {
                    mma_bf16(acc[mf][2*q+0], fAhi[mf], &fB[q][0]);
                    mma_bf16(acc[mf][2*q+1], fAhi[mf], &fB[q][2]);
                }
        }
        __syncthreads();   // all reads of stage c&1 done before it is refilled
    }

    // Epilogue: scatter accumulators to g_sup
    const int quad = lane >> 2;
    const int tq   = lane & 3;
    #pragma unroll
    for (int mf = 0; mf < 2; mf++) {
        #pragma unroll
        for (int nf = 0; nf < 6; nf++) {
            #pragma unroll
            for (int r = 0; r < 4; r++) {
                int m = bm*128 + wm*32 + mf*16 + ((r >> 1) << 3) + quad;  // graph node n
                int col = bn*96 + wn*48 + nf*8 + tq*2 + (r & 1);
                int b = col / Pq;
                int p = col - b*Pq;
                g_sup[(b*Nq + m)*KSTRIDE + kk*Pq + p] = acc[mf][nf][r];
            }
        }
    }
}

// ---------------------------------------------------------------------------
// GEMM2 (register-tiled SIMT) + fused epilogues (writes combT hi/lo splits).
// ---------------------------------------------------------------------------
#define BM 128
#define BN 64
#define BKT 16

template<int OUT, bool GATE>
__global__ __launch_bounds__(256) void gemm2t_kernel(const float* __restrict__ W,
                                                     const float* __restrict__ bias,
                                                     float* __restrict__ out, int is_last) {
    const int bn = blockIdx.x;
    const int bm = blockIdx.y;
    const float* A  = g_sup + bm*BM*KSTRIDE;
    const float* Bp = W + bn*BN;

    __shared__ float As[BKT][BM + 4];
    __shared__ float Bs[BKT][BN];

    const int tid  = threadIdx.x;
    const int tidm = tid >> 4;
    const int tidn = tid & 15;

    float acc[8][4];
    #pragma unroll
    for (int j = 0; j < 4; j++) {
        float bv = bias[bn*BN + tidn*4 + j];
        #pragma unroll
        for (int i = 0; i < 8; i++) acc[i][j] = bv;
    }

    for (int kt = 0; kt < KLOOP; kt += BKT) {
        #pragma unroll
        for (int l = 0; l < 2; l++) {
            int q   = tid + l*256;
            int row = q >> 2;
            int c4  = q & 3;
            float4 v = *(const float4*)(A + row*KSTRIDE + kt + c4*4);
            As[c4*4+0][row] = v.x;
            As[c4*4+1][row] = v.y;
            As[c4*4+2][row] = v.z;
            As[c4*4+3][row] = v.w;
        }
        {
            int row = tid >> 4;
            int c4  = tid & 15;
            float4 v = make_float4(0.f, 0.f, 0.f, 0.f);
            if (kt + row < KP)
                v = *(const float4*)(Bp + (kt + row)*OUT + c4*4);
            *(float4*)&Bs[row][c4*4] = v;
        }
        __syncthreads();

        #pragma unroll
        for (int kq = 0; kq < BKT; kq++) {
            float a[8], bb[4];
            #pragma unroll
            for (int i = 0; i < 8; i++) a[i] = As[kq][tidm*8 + i];
            #pragma unroll
            for (int j = 0; j < 4; j++) bb[j] = Bs[kq][tidn*4 + j];
            #pragma unroll
            for (int i = 0; i < 8; i++)
                #pragma unroll
                for (int j = 0; j < 4; j++)
                    acc[i][j] = fmaf(a[i], bb[j], acc[i][j]);
        }
        __syncthreads();
    }

    #pragma unroll
    for (int i = 0; i < 8; i++) {
        int row = bm*BM + tidm*8 + i;   // b*N + n
        int b = row >> 9;
        int n = row & (Nq - 1);
        #pragma unroll
        for (int j = 0; j < 4; j++) {
            int o = bn*BN + tidn*4 + j;
            if (GATE) {
                float zv = 1.0f / (1.0f + __expf(-acc[i][j]));
                if (o < Hq) {
                    g_z[row*Hq + o] = zv;
                } else {
                    int hid = o - Hq;
                    float rh = zv * g_h[row*Hq + hid];
                    __nv_bfloat16 hi, lo;
                    split_bf16(rh, hi, lo);
                    int ct = (b*Pq + Cq + hid)*Nq + n;
                    g_ctHi[ct] = hi;
                    g_ctLo[ct] = lo;
                }
            } else {
                float hc   = tanhf(acc[i][j]);
                float zv   = g_z[row*Hq + o];
                float hold = g_h[row*Hq + o];
                float hnew = (1.0f - zv)*hold + zv*hc;
                g_h[row*Hq + o] = hnew;
                __nv_bfloat16 hi, lo;
                split_bf16(hnew, hi, lo);
                int ct = (b*Pq + Cq + o)*Nq + n;
                g_ctHi[ct] = hi;
                g_ctLo[ct] = lo;
                if (is_last) out[row*Hq + o] = hnew;
            }
        }
    }
}

// ---------------------------------------------------------------------------
// kernel_launch
// Inputs: G, x_seq, init_h, W_gate, b_gate, W_update, b_update
// ---------------------------------------------------------------------------
extern "C" void kernel_launch(void* const* d_in, const int* in_sizes, int n_in,
                              void* d_out, int out_size) {
    const float* G        = (const float*)d_in[0];
    const float* x_seq    = (const float*)d_in[1];
    const float* init_h   = (const float*)d_in[2];
    const float* W_gate   = (const float*)d_in[3];
    const float* b_gate   = (const float*)d_in[4];
    const float* W_update = (const float*)d_in[5];
    const float* b_update = (const float*)d_in[6];
    float* out = (float*)d_out;

    cudaFuncSetAttribute(gemm1_mma_kernel,
                         cudaFuncAttributeMaxDynamicSharedMemorySize, SMEM_G1);

    prep_g_kernel<<<(Kq*Nq*Nq + 255)/256, 256>>>(G);
    init_kernel<<<(Bq*Nq*Hq + 255)/256, 256>>>(init_h);

    dim3 g1(NCOLS/96, Nq/128, Kq);       // (22, 4, 3)
    dim3 g2g(OUTG/BN, NROWS/BM);         // (2, 128)
    dim3 g2u(Hq/BN,  NROWS/BM);          // (1, 128)
    for (int t = 0; t < Tq; t++) {
        set_x_kernel<<<(Bq*Nq*Cq + 255)/256, 256>>>(x_seq, t);
        gemm1_mma_kernel<<<g1, 256, SMEM_G1>>>();
        gemm2t_kernel<OUTG, true><<<g2g, 256>>>(W_gate, b_gate, out, 0);
        gemm1_mma_kernel<<<g1, 256, SMEM_G1>>>();
        gemm2t_kernel<Hq, false><<<g2u, 256>>>(W_update, b_update, out, t == Tq - 1);
    }
}

// round 10
// speedup vs baseline: 1.6558x; 1.0623x over previous
#include <cuda_runtime.h>
#include <cuda_bf16.h>
#include <cstdint>
#include <math.h>

// Problem constants
#define Bq 32
#define Tq 12
#define Nq 512
#define Cq 2
#define Hq 64
#define Kq 3
#define Pq 66            // C + H
#define NCOLS (Bq*Pq)    // 2112 columns of Combined
#define KP  (Kq*Pq)      // 198
#define KS2 208          // sup row stride in bf16 (416 B, 16B aligned)
#define OUTG (2*Hq)      // 128
#define NROWS (Bq*Nq)    // 16384

// ---------------- device state (no allocations allowed) ----------------
__device__ float g_h[Bq*Nq*Hq];                 // hidden state fp32
__device__ float g_z[Bq*Nq*Hq];                 // gate z
__device__ __nv_bfloat16 g_gHi[Kq*Nq*Nq];       // G split hi [k][n][j]
__device__ __nv_bfloat16 g_gLo[Kq*Nq*Nq];       // G split lo
__device__ __nv_bfloat16 g_ctHi[NCOLS*Nq];      // Combined^T hi [col][j]
__device__ __nv_bfloat16 g_ctLo[NCOLS*Nq];      // Combined^T lo
__device__ __nv_bfloat16 g_supHi[NROWS*KS2];    // sup hi [row][k] (pad cols stay 0)
__device__ __nv_bfloat16 g_supLo[NROWS*KS2];    // sup lo
__device__ __nv_bfloat16 g_WtgHi[OUTG*KS2];     // W_gate^T hi [o][k], zero-padded
__device__ __nv_bfloat16 g_WtgLo[OUTG*KS2];
__device__ __nv_bfloat16 g_WtuHi[Hq*KS2];       // W_update^T hi
__device__ __nv_bfloat16 g_WtuLo[Hq*KS2];

__device__ __forceinline__ void split_bf16(float v, __nv_bfloat16& hi, __nv_bfloat16& lo) {
    hi = __float2bfloat16(v);
    lo = __float2bfloat16(v - __bfloat162float(hi));
}

// ---------------- prep: split G; build transposed split W ----------------
__global__ void prep_g_kernel(const float* __restrict__ G) {
    int idx = blockIdx.x * blockDim.x + threadIdx.x;
    if (idx >= Kq*Nq*Nq) return;
    __nv_bfloat16 hi, lo;
    split_bf16(G[idx], hi, lo);
    g_gHi[idx] = hi;
    g_gLo[idx] = lo;
}

__global__ void prep_w_kernel(const float* __restrict__ Wg, const float* __restrict__ Wu) {
    int idx = blockIdx.x * blockDim.x + threadIdx.x;
    if (idx < OUTG*KS2) {
        int o = idx / KS2, k = idx % KS2;
        float v = (k < KP) ? Wg[k*OUTG + o] : 0.0f;
        __nv_bfloat16 hi, lo; split_bf16(v, hi, lo);
        g_WtgHi[idx] = hi; g_WtgLo[idx] = lo;
    } else if (idx < OUTG*KS2 + Hq*KS2) {
        int q = idx - OUTG*KS2;
        int o = q / KS2, k = q % KS2;
        float v = (k < KP) ? Wu[k*Hq + o] : 0.0f;
        __nv_bfloat16 hi, lo; split_bf16(v, hi, lo);
        g_WtuHi[q] = hi; g_WtuLo[q] = lo;
    }
}

// ---------------- init / set_x ----------------
__global__ void init_kernel(const float* __restrict__ init_h) {
    int idx = blockIdx.x * blockDim.x + threadIdx.x;
    if (idx >= Bq*Nq*Hq) return;
    float v = init_h[idx];
    g_h[idx] = v;
    int hid = idx % Hq;
    int row = idx / Hq;
    int b = row / Nq;
    int n = row % Nq;
    __nv_bfloat16 hi, lo; split_bf16(v, hi, lo);
    int ct = (b*Pq + Cq + hid)*Nq + n;
    g_ctHi[ct] = hi; g_ctLo[ct] = lo;
}

__global__ void set_x_kernel(const float* __restrict__ x_seq, int t) {
    int idx = blockIdx.x * blockDim.x + threadIdx.x;
    if (idx >= Bq*Nq*Cq) return;
    int p = idx % Cq;
    int rest = idx / Cq;
    int n = rest % Nq;
    int b = rest / Nq;
    float v = x_seq[((b*Tq + t)*Nq + n)*Cq + p];
    __nv_bfloat16 hi, lo; split_bf16(v, hi, lo);
    int ct = (b*Pq + p)*Nq + n;
    g_ctHi[ct] = hi; g_ctLo[ct] = lo;
}

// ---------------- shared mma helpers ----------------
__device__ __forceinline__ void ldm_x4(uint32_t* r, uint32_t addr) {
    asm volatile("ldmatrix.sync.aligned.m8n8.x4.shared.b16 {%0,%1,%2,%3}, [%4];"
                 : "=r"(r[0]), "=r"(r[1]), "=r"(r[2]), "=r"(r[3]) : "r"(addr));
}
__device__ __forceinline__ void mma_bf16(float* c, const uint32_t* a, const uint32_t* b) {
    asm volatile("mma.sync.aligned.m16n8k16.row.col.f32.bf16.bf16.f32 "
                 "{%0,%1,%2,%3}, {%4,%5,%6,%7}, {%8,%9}, {%0,%1,%2,%3};"
                 : "+f"(c[0]), "+f"(c[1]), "+f"(c[2]), "+f"(c[3])
                 : "r"(a[0]), "r"(a[1]), "r"(a[2]), "r"(a[3]), "r"(b[0]), "r"(b[1]));
}
__device__ __forceinline__ uint32_t smem_u32(const void* p) {
    uint32_t a;
    asm("{ .reg .u64 t; cvta.to.shared.u64 t, %1; cvt.u32.u64 %0, t; }" : "=r"(a) : "l"(p));
    return a;
}
__device__ __forceinline__ void cp16(uint32_t dst, const void* src) {
    asm volatile("cp.async.cg.shared.global [%0], [%1], 16;" :: "r"(dst), "l"(src));
}
#define CP_COMMIT() asm volatile("cp.async.commit_group;" ::: "memory")
#define CP_WAIT1()  asm volatile("cp.async.wait_group 1;" ::: "memory")
#define CP_WAIT0()  asm volatile("cp.async.wait_group 0;" ::: "memory")

// ---------------------------------------------------------------------------
// GEMM1: Sup = G[k] @ Comb, split-bf16 3-pass, cp.async double-buffered.
// CTA tile 128x96, K-chunk 32, grid (22,4,3), 256 threads.
// Epilogue stores bf16 hi/lo sup.
// ---------------------------------------------------------------------------
#define ROWB 80
#define OFF_AHI 0
#define OFF_ALO 10240
#define OFF_BHI 20480
#define OFF_BLO 28160
#define STGSZ   35840
#define SMEM_G1 (2*STGSZ)

__global__ __launch_bounds__(256) void gemm1_mma_kernel() {
    extern __shared__ char smg[];
    const int kk = blockIdx.z;
    const int bm = blockIdx.y;
    const int bn = blockIdx.x;
    const int tid  = threadIdx.x;
    const int wid  = tid >> 5;
    const int lane = tid & 31;
    const int wm = wid & 3;
    const int wn = wid >> 2;
    const uint32_t sm0 = smem_u32(smg);

    const __nv_bfloat16* Ahi0 = g_gHi + kk*Nq*Nq + bm*128*Nq;
    const __nv_bfloat16* Alo0 = g_gLo + kk*Nq*Nq + bm*128*Nq;
    const __nv_bfloat16* Bhi0 = g_ctHi + bn*96*Nq;
    const __nv_bfloat16* Blo0 = g_ctLo + bn*96*Nq;

    const int rA0 = tid >> 2,          qA0 = (tid & 3);
    const int rA1 = (tid + 256) >> 2,  qA1 = (tid & 3);
    const int rB0 = tid >> 2,          qB0 = (tid & 3);
    const int rB1 = (tid + 256) >> 2,  qB1 = (tid & 3);

    float acc[2][6][4];
    #pragma unroll
    for (int i = 0; i < 2; i++)
        #pragma unroll
        for (int j = 0; j < 6; j++)
            #pragma unroll
            for (int r = 0; r < 4; r++) acc[i][j][r] = 0.0f;

    const uint32_t aOff = (uint32_t)((lane & 15) * ROWB + (lane >> 4) * 16);
    const uint32_t bOff = (uint32_t)(((lane & 7) + ((lane >> 4) << 3)) * ROWB
                                     + (((lane >> 3) & 1) * 16));

    {   // prefetch chunk 0
        const uint32_t base = sm0;
        cp16(base + OFF_AHI + rA0*ROWB + qA0*16, Ahi0 + rA0*Nq + qA0*8);
        cp16(base + OFF_ALO + rA0*ROWB + qA0*16, Alo0 + rA0*Nq + qA0*8);
        cp16(base + OFF_AHI + rA1*ROWB + qA1*16, Ahi0 + rA1*Nq + qA1*8);
        cp16(base + OFF_ALO + rA1*ROWB + qA1*16, Alo0 + rA1*Nq + qA1*8);
        cp16(base + OFF_BHI + rB0*ROWB + qB0*16, Bhi0 + rB0*Nq + qB0*8);
        cp16(base + OFF_BLO + rB0*ROWB + qB0*16, Blo0 + rB0*Nq + qB0*8);
        if (tid < 128) {
            cp16(base + OFF_BHI + rB1*ROWB + qB1*16, Bhi0 + rB1*Nq + qB1*8);
            cp16(base + OFF_BLO + rB1*ROWB + qB1*16, Blo0 + rB1*Nq + qB1*8);
        }
        CP_COMMIT();
    }

    for (int c = 0; c < 16; c++) {
        if (c < 15) {
            const uint32_t base = sm0 + ((c + 1) & 1) * STGSZ;
            const int kt = (c + 1) * 32;
            cp16(base + OFF_AHI + rA0*ROWB + qA0*16, Ahi0 + rA0*Nq + kt + qA0*8);
            cp16(base + OFF_ALO + rA0*ROWB + qA0*16, Alo0 + rA0*Nq + kt + qA0*8);
            cp16(base + OFF_AHI + rA1*ROWB + qA1*16, Ahi0 + rA1*Nq + kt + qA1*8);
            cp16(base + OFF_ALO + rA1*ROWB + qA1*16, Alo0 + rA1*Nq + kt + qA1*8);
            cp16(base + OFF_BHI + rB0*ROWB + qB0*16, Bhi0 + rB0*Nq + kt + qB0*8);
            cp16(base + OFF_BLO + rB0*ROWB + qB0*16, Blo0 + rB0*Nq + kt + qB0*8);
            if (tid < 128) {
                cp16(base + OFF_BHI + rB1*ROWB + qB1*16, Bhi0 + rB1*Nq + kt + qB1*8);
                cp16(base + OFF_BLO + rB1*ROWB + qB1*16, Blo0 + rB1*Nq + kt + qB1*8);
            }
            CP_COMMIT();
            CP_WAIT1();
        } else {
            CP_WAIT0();
        }
        __syncthreads();

        const uint32_t base = sm0 + (c & 1) * STGSZ;
        const uint32_t uAhi = base + OFF_AHI;
        const uint32_t uAlo = base + OFF_ALO;
        const uint32_t uBhi = base + OFF_BHI;
        const uint32_t uBlo = base + OFF_BLO;

        #pragma unroll
        for (int ks = 0; ks < 2; ks++) {
            const uint32_t kByte = (uint32_t)(ks * 32);
            uint32_t fAhi[2][4], fAlo[2][4], fB[3][4];

            #pragma unroll
            for (int mf = 0; mf < 2; mf++)
                ldm_x4(fAhi[mf], uAhi + (wm*32 + mf*16)*ROWB + aOff + kByte);
            #pragma unroll
            for (int q = 0; q < 3; q++)
                ldm_x4(fB[q], uBhi + (wn*48 + q*16)*ROWB + bOff + kByte);
            #pragma unroll
            for (int mf = 0; mf < 2; mf++)
                #pragma unroll
                for (int q = 0; q < 3; q++) {
                    mma_bf16(acc[mf][2*q+0], fAhi[mf], &fB[q][0]);
                    mma_bf16(acc[mf][2*q+1], fAhi[mf], &fB[q][2]);
                }

            #pragma unroll
            for (int mf = 0; mf < 2; mf++)
                ldm_x4(fAlo[mf], uAlo + (wm*32 + mf*16)*ROWB + aOff + kByte);
            #pragma unroll
            for (int mf = 0; mf < 2; mf++)
                #pragma unroll
                for (int q = 0; q < 3; q++) {
                    mma_bf16(acc[mf][2*q+0], fAlo[mf], &fB[q][0]);
                    mma_bf16(acc[mf][2*q+1], fAlo[mf], &fB[q][2]);
                }

            #pragma unroll
            for (int q = 0; q < 3; q++)
                ldm_x4(fB[q], uBlo + (wn*48 + q*16)*ROWB + bOff + kByte);
            #pragma unroll
            for (int mf = 0; mf < 2; mf++)
                #pragma unroll
                for (int q = 0; q < 3; q++) {
                    mma_bf16(acc[mf][2*q+0], fAhi[mf], &fB[q][0]);
                    mma_bf16(acc[mf][2*q+1], fAhi[mf], &fB[q][2]);
                }
        }
        __syncthreads();
    }

    // Epilogue: split-store to bf16 sup
    const int quad = lane >> 2;
    const int tq   = lane & 3;
    #pragma unroll
    for (int mf = 0; mf < 2; mf++) {
        #pragma unroll
        for (int nf = 0; nf < 6; nf++) {
            #pragma unroll
            for (int r = 0; r < 4; r++) {
                int m = bm*128 + wm*32 + mf*16 + ((r >> 1) << 3) + quad;
                int col = bn*96 + wn*48 + nf*8 + tq*2 + (r & 1);
                int b = col / Pq;
                int p = col - b*Pq;
                __nv_bfloat16 hi, lo;
                split_bf16(acc[mf][nf][r], hi, lo);
                int idx = (b*Nq + m)*KS2 + kk*Pq + p;
                g_supHi[idx] = hi;
                g_supLo[idx] = lo;
            }
        }
    }
}

// ---------------------------------------------------------------------------
// GEMM2 via mma.sync, split-bf16 3-pass, cp.async double-buffered.
// A = sup (bf16 hi/lo, stride 208), B = Wt (bf16 hi/lo, [o][k]).
// CTA tile 128 x OUT, 13 k16 chunks. grid = 128. 256 threads.
// Smem row stride 48 B (16B-aligned for cp.async/ldmatrix; banks conflict-free).
// ---------------------------------------------------------------------------
#define RB2 48

template<int OUT, bool GATE>
__global__ __launch_bounds__(256) void gemm2m_kernel(const float* __restrict__ bias,
                                                     float* __restrict__ out, int is_last) {
    constexpr int NWN = OUT/64;        // warps in N: 2 or 1
    constexpr int NWM = 8/NWN;         // warps in M: 4 or 8
    constexpr int MT  = 128/NWM;       // warp M tile: 32 or 16
    constexpr int MF  = MT/16;         // m16 frags: 2 or 1
    constexpr int OFF2_ALO = 128*RB2;              // 6144
    constexpr int OFF2_WHI = 2*128*RB2;            // 12288
    constexpr int OFF2_WLO = 2*128*RB2 + OUT*RB2;
    constexpr int STG2     = 2*128*RB2 + 2*OUT*RB2;

    __shared__ char smg[2*STG2];

    const int bm = blockIdx.x;         // 0..127
    const int tid  = threadIdx.x;
    const int wid  = tid >> 5;
    const int lane = tid & 31;
    const int wm = wid % NWM;
    const int wn = wid / NWM;
    const uint32_t sm0 = smem_u32(smg);

    const __nv_bfloat16* WtHi = GATE ? g_WtgHi : g_WtuHi;
    const __nv_bfloat16* WtLo = GATE ? g_WtgLo : g_WtuLo;
    const __nv_bfloat16* AHi0 = g_supHi + (size_t)bm*128*KS2;
    const __nv_bfloat16* ALo0 = g_supLo + (size_t)bm*128*KS2;

    // staging indices: rows x 2 halves (16 B each covers 8 bf16 of the 16 per row)
    const int rA = tid >> 1, hA = tid & 1;

    float acc[MF][8][4];
    #pragma unroll
    for (int mf = 0; mf < MF; mf++)
        #pragma unroll
        for (int nf = 0; nf < 8; nf++)
            #pragma unroll
            for (int r = 0; r < 4; r++)
                acc[mf][nf][r] = bias[wn*64 + nf*8 + (lane & 3)*2 + (r & 1)];

    const uint32_t aOff = (uint32_t)((lane & 15) * RB2 + (lane >> 4) * 16);
    const uint32_t bOff = (uint32_t)(((lane & 7) + ((lane >> 4) << 3)) * RB2
                                     + (((lane >> 3) & 1) * 16));

    // prefetch chunk 0
    {
        const uint32_t base = sm0;
        cp16(base + 0        + rA*RB2 + hA*16, AHi0 + rA*KS2 + hA*8);
        cp16(base + OFF2_ALO + rA*RB2 + hA*16, ALo0 + rA*KS2 + hA*8);
        if (OUT == 128) {
            cp16(base + OFF2_WHI + rA*RB2 + hA*16, WtHi + rA*KS2 + hA*8);
            cp16(base + OFF2_WLO + rA*RB2 + hA*16, WtLo + rA*KS2 + hA*8);
        } else if (tid < 128) {
            cp16(base + OFF2_WHI + rA*RB2 + hA*16, WtHi + rA*KS2 + hA*8);
            cp16(base + OFF2_WLO + rA*RB2 + hA*16, WtLo + rA*KS2 + hA*8);
        }
        CP_COMMIT();
    }

    for (int c = 0; c < 13; c++) {
        if (c < 12) {
            const uint32_t base = sm0 + ((c + 1) & 1) * STG2;
            const int kt = (c + 1) * 16;
            cp16(base + 0        + rA*RB2 + hA*16, AHi0 + rA*KS2 + kt + hA*8);
            cp16(base + OFF2_ALO + rA*RB2 + hA*16, ALo0 + rA*KS2 + kt + hA*8);
            if (OUT == 128) {
                cp16(base + OFF2_WHI + rA*RB2 + hA*16, WtHi + rA*KS2 + kt + hA*8);
                cp16(base + OFF2_WLO + rA*RB2 + hA*16, WtLo + rA*KS2 + kt + hA*8);
            } else if (tid < 128) {
                cp16(base + OFF2_WHI + rA*RB2 + hA*16, WtHi + rA*KS2 + kt + hA*8);
                cp16(base + OFF2_WLO + rA*RB2 + hA*16, WtLo + rA*KS2 + kt + hA*8);
            }
            CP_COMMIT();
            CP_WAIT1();
        } else {
            CP_WAIT0();
        }
        __syncthreads();

        const uint32_t base = sm0 + (c & 1) * STG2;
        uint32_t fAhi[MF][4], fAlo[MF][4], fW[4][4];

        #pragma unroll
        for (int mf = 0; mf < MF; mf++)
            ldm_x4(fAhi[mf], base + 0 + (wm*MT + mf*16)*RB2 + aOff);
        #pragma unroll
        for (int q = 0; q < 4; q++)
            ldm_x4(fW[q], base + OFF2_WHI + (wn*64 + q*16)*RB2 + bOff);
        #pragma unroll
        for (int mf = 0; mf < MF; mf++)
            #pragma unroll
            for (int q = 0; q < 4; q++) {
                mma_bf16(acc[mf][2*q+0], fAhi[mf], &fW[q][0]);
                mma_bf16(acc[mf][2*q+1], fAhi[mf], &fW[q][2]);
            }

        #pragma unroll
        for (int mf = 0; mf < MF; mf++)
            ldm_x4(fAlo[mf], base + OFF2_ALO + (wm*MT + mf*16)*RB2 + aOff);
        #pragma unroll
        for (int mf = 0; mf < MF; mf++)
            #pragma unroll
            for (int q = 0; q < 4; q++) {
                mma_bf16(acc[mf][2*q+0], fAlo[mf], &fW[q][0]);
                mma_bf16(acc[mf][2*q+1], fAlo[mf], &fW[q][2]);
            }

        #pragma unroll
        for (int q = 0; q < 4; q++)
            ldm_x4(fW[q], base + OFF2_WLO + (wn*64 + q*16)*RB2 + bOff);
        #pragma unroll
        for (int mf = 0; mf < MF; mf++)
            #pragma unroll
            for (int q = 0; q < 4; q++) {
                mma_bf16(acc[mf][2*q+0], fAhi[mf], &fW[q][0]);
                mma_bf16(acc[mf][2*q+1], fAhi[mf], &fW[q][2]);
            }
        __syncthreads();
    }

    // Fused GRU epilogue
    const int quad = lane >> 2;
    const int tq   = lane & 3;
    #pragma unroll
    for (int mf = 0; mf < MF; mf++) {
        #pragma unroll
        for (int nf = 0; nf < 8; nf++) {
            #pragma unroll
            for (int r = 0; r < 4; r++) {
                int row = bm*128 + wm*MT + mf*16 + ((r >> 1) << 3) + quad;  // b*N + n
                int o   = wn*64 + nf*8 + tq*2 + (r & 1);
                int b = row >> 9;
                int n = row & (Nq - 1);
                float v = acc[mf][nf][r];
                if (GATE) {
                    float zv = 1.0f / (1.0f + __expf(-v));
                    if (o < Hq) {
                        g_z[row*Hq + o] = zv;
                    } else {
                        int hid = o - Hq;
                        float rh = zv * g_h[row*Hq + hid];
                        __nv_bfloat16 hi, lo; split_bf16(rh, hi, lo);
                        int ct = (b*Pq + Cq + hid)*Nq + n;
                        g_ctHi[ct] = hi; g_ctLo[ct] = lo;
                    }
                } else {
                    float hc   = tanhf(v);
                    float zv   = g_z[row*Hq + o];
                    float hold = g_h[row*Hq + o];
                    float hnew = (1.0f - zv)*hold + zv*hc;
                    g_h[row*Hq + o] = hnew;
                    __nv_bfloat16 hi, lo; split_bf16(hnew, hi, lo);
                    int ct = (b*Pq + Cq + o)*Nq + n;
                    g_ctHi[ct] = hi; g_ctLo[ct] = lo;
                    if (is_last) out[row*Hq + o] = hnew;
                }
            }
        }
    }
}

// ---------------------------------------------------------------------------
// kernel_launch
// Inputs: G, x_seq, init_h, W_gate, b_gate, W_update, b_update
// ---------------------------------------------------------------------------
extern "C" void kernel_launch(void* const* d_in, const int* in_sizes, int n_in,
                              void* d_out, int out_size) {
    const float* G        = (const float*)d_in[0];
    const float* x_seq    = (const float*)d_in[1];
    const float* init_h   = (const float*)d_in[2];
    const float* W_gate   = (const float*)d_in[3];
    const float* b_gate   = (const float*)d_in[4];
    const float* W_update = (const float*)d_in[5];
    const float* b_update = (const float*)d_in[6];
    float* out = (float*)d_out;

    cudaFuncSetAttribute(gemm1_mma_kernel,
                         cudaFuncAttributeMaxDynamicSharedMemorySize, SMEM_G1);

    prep_g_kernel<<<(Kq*Nq*Nq + 255)/256, 256>>>(G);
    prep_w_kernel<<<((OUTG + Hq)*KS2 + 255)/256, 256>>>(W_gate, W_update);
    init_kernel<<<(Bq*Nq*Hq + 255)/256, 256>>>(init_h);

    dim3 g1(NCOLS/96, Nq/128, Kq);   // (22, 4, 3)
    for (int t = 0; t < Tq; t++) {
        set_x_kernel<<<(Bq*Nq*Cq + 255)/256, 256>>>(x_seq, t);
        gemm1_mma_kernel<<<g1, 256, SMEM_G1>>>();
        gemm2m_kernel<OUTG, true><<<NROWS/128, 256>>>(b_gate, out, 0);
        gemm1_mma_kernel<<<g1, 256, SMEM_G1>>>();
        gemm2m_kernel<Hq, false><<<NROWS/128, 256>>>(b_update, out, t == Tq - 1);
    }
}

// round 11
// speedup vs baseline: 1.9250x; 1.1625x over previous
#include <cuda_runtime.h>
#include <cuda_bf16.h>
#include <cstdint>
#include <math.h>

// Problem constants
#define Bq 32
#define Tq 12
#define Nq 512
#define Cq 2
#define Hq 64
#define Kq 3
#define Pq 66            // C + H
#define NCOLS (Bq*Pq)    // 2112 columns of Combined
#define KP  (Kq*Pq)      // 198
#define KS2 208          // sup row stride in bf16 (416 B, 16B aligned)
#define OUTG (2*Hq)      // 128
#define NROWS (Bq*Nq)    // 16384

// ---------------- device state (no allocations allowed) ----------------
__device__ float g_h[Bq*Nq*Hq];                 // hidden state fp32
__device__ float g_z[Bq*Nq*Hq];                 // gate z
__device__ __nv_bfloat16 g_gHi[Kq*Nq*Nq];       // G split hi [k][n][j]
__device__ __nv_bfloat16 g_gLo[Kq*Nq*Nq];       // G split lo
__device__ __nv_bfloat16 g_ctHi[NCOLS*Nq];      // Combined^T hi [col][j]
__device__ __nv_bfloat16 g_ctLo[NCOLS*Nq];      // Combined^T lo
__device__ __nv_bfloat16 g_supHi[NROWS*KS2];    // sup hi [row][k] (pad cols stay 0)
__device__ __nv_bfloat16 g_supLo[NROWS*KS2];    // sup lo
__device__ __nv_bfloat16 g_WtgHi[OUTG*KS2];     // W_gate^T hi [o][k], zero-padded
__device__ __nv_bfloat16 g_WtgLo[OUTG*KS2];
__device__ __nv_bfloat16 g_WtuHi[Hq*KS2];       // W_update^T hi
__device__ __nv_bfloat16 g_WtuLo[Hq*KS2];

__device__ __forceinline__ void split_bf16(float v, __nv_bfloat16& hi, __nv_bfloat16& lo) {
    hi = __float2bfloat16(v);
    lo = __float2bfloat16(v - __bfloat162float(hi));
}

// ---------------- prep: split G; build transposed split W ----------------
__global__ void prep_g_kernel(const float* __restrict__ G) {
    int idx = blockIdx.x * blockDim.x + threadIdx.x;
    if (idx >= Kq*Nq*Nq) return;
    __nv_bfloat16 hi, lo;
    split_bf16(G[idx], hi, lo);
    g_gHi[idx] = hi;
    g_gLo[idx] = lo;
}

__global__ void prep_w_kernel(const float* __restrict__ Wg, const float* __restrict__ Wu) {
    int idx = blockIdx.x * blockDim.x + threadIdx.x;
    if (idx < OUTG*KS2) {
        int o = idx / KS2, k = idx % KS2;
        float v = (k < KP) ? Wg[k*OUTG + o] : 0.0f;
        __nv_bfloat16 hi, lo; split_bf16(v, hi, lo);
        g_WtgHi[idx] = hi; g_WtgLo[idx] = lo;
    } else if (idx < OUTG*KS2 + Hq*KS2) {
        int q = idx - OUTG*KS2;
        int o = q / KS2, k = q % KS2;
        float v = (k < KP) ? Wu[k*Hq + o] : 0.0f;
        __nv_bfloat16 hi, lo; split_bf16(v, hi, lo);
        g_WtuHi[q] = hi; g_WtuLo[q] = lo;
    }
}

// ---------------- init / set_x ----------------
__global__ void init_kernel(const float* __restrict__ init_h) {
    int idx = blockIdx.x * blockDim.x + threadIdx.x;
    if (idx >= Bq*Nq*Hq) return;
    float v = init_h[idx];
    g_h[idx] = v;
    int hid = idx % Hq;
    int row = idx / Hq;
    int b = row / Nq;
    int n = row % Nq;
    __nv_bfloat16 hi, lo; split_bf16(v, hi, lo);
    int ct = (b*Pq + Cq + hid)*Nq + n;
    g_ctHi[ct] = hi; g_ctLo[ct] = lo;
}

__global__ void set_x_kernel(const float* __restrict__ x_seq, int t) {
    int idx = blockIdx.x * blockDim.x + threadIdx.x;
    if (idx >= Bq*Nq*Cq) return;
    int p = idx % Cq;
    int rest = idx / Cq;
    int n = rest % Nq;
    int b = rest / Nq;
    float v = x_seq[((b*Tq + t)*Nq + n)*Cq + p];
    __nv_bfloat16 hi, lo; split_bf16(v, hi, lo);
    int ct = (b*Pq + p)*Nq + n;
    g_ctHi[ct] = hi; g_ctLo[ct] = lo;
}

// ---------------- shared mma helpers ----------------
__device__ __forceinline__ void ldm_x4(uint32_t* r, uint32_t addr) {
    asm volatile("ldmatrix.sync.aligned.m8n8.x4.shared.b16 {%0,%1,%2,%3}, [%4];"
                 : "=r"(r[0]), "=r"(r[1]), "=r"(r[2]), "=r"(r[3]) : "r"(addr));
}
__device__ __forceinline__ void mma_bf16(float* c, const uint32_t* a, const uint32_t* b) {
    asm volatile("mma.sync.aligned.m16n8k16.row.col.f32.bf16.bf16.f32 "
                 "{%0,%1,%2,%3}, {%4,%5,%6,%7}, {%8,%9}, {%0,%1,%2,%3};"
                 : "+f"(c[0]), "+f"(c[1]), "+f"(c[2]), "+f"(c[3])
                 : "r"(a[0]), "r"(a[1]), "r"(a[2]), "r"(a[3]), "r"(b[0]), "r"(b[1]));
}
__device__ __forceinline__ uint32_t smem_u32(const void* p) {
    uint32_t a;
    asm("{ .reg .u64 t; cvta.to.shared.u64 t, %1; cvt.u32.u64 %0, t; }" : "=r"(a) : "l"(p));
    return a;
}
__device__ __forceinline__ void cp16(uint32_t dst, const void* src) {
    asm volatile("cp.async.cg.shared.global [%0], [%1], 16;" :: "r"(dst), "l"(src));
}
#define CP_COMMIT() asm volatile("cp.async.commit_group;" ::: "memory")
#define CP_WAIT1()  asm volatile("cp.async.wait_group 1;" ::: "memory")
#define CP_WAIT0()  asm volatile("cp.async.wait_group 0;" ::: "memory")

// ---------------------------------------------------------------------------
// GEMM1: Sup = G[k] @ Comb, split-bf16 3-pass, cp.async double-buffered.
// CTA tile 128x96, K-chunk 32, grid (22,4,3), 256 threads.
// Epilogue: stage fp32 in smem, then coalesced split-store to bf16 sup.
// ---------------------------------------------------------------------------
#define ROWB 80
#define OFF_AHI 0
#define OFF_ALO 10240
#define OFF_BHI 20480
#define OFF_BLO 28160
#define STGSZ   35840
#define SMEM_G1 (2*STGSZ)   // 71680 >= 128*97*4 epilogue buffer

__global__ __launch_bounds__(256) void gemm1_mma_kernel() {
    extern __shared__ char smg[];
    const int kk = blockIdx.z;
    const int bm = blockIdx.y;
    const int bn = blockIdx.x;
    const int tid  = threadIdx.x;
    const int wid  = tid >> 5;
    const int lane = tid & 31;
    const int wm = wid & 3;
    const int wn = wid >> 2;
    const uint32_t sm0 = smem_u32(smg);

    const __nv_bfloat16* Ahi0 = g_gHi + kk*Nq*Nq + bm*128*Nq;
    const __nv_bfloat16* Alo0 = g_gLo + kk*Nq*Nq + bm*128*Nq;
    const __nv_bfloat16* Bhi0 = g_ctHi + bn*96*Nq;
    const __nv_bfloat16* Blo0 = g_ctLo + bn*96*Nq;

    const int rA0 = tid >> 2,          qA0 = (tid & 3);
    const int rA1 = (tid + 256) >> 2,  qA1 = (tid & 3);
    const int rB0 = tid >> 2,          qB0 = (tid & 3);
    const int rB1 = (tid + 256) >> 2,  qB1 = (tid & 3);

    float acc[2][6][4];
    #pragma unroll
    for (int i = 0; i < 2; i++)
        #pragma unroll
        for (int j = 0; j < 6; j++)
            #pragma unroll
            for (int r = 0; r < 4; r++) acc[i][j][r] = 0.0f;

    const uint32_t aOff = (uint32_t)((lane & 15) * ROWB + (lane >> 4) * 16);
    const uint32_t bOff = (uint32_t)(((lane & 7) + ((lane >> 4) << 3)) * ROWB
                                     + (((lane >> 3) & 1) * 16));

    {   // prefetch chunk 0
        const uint32_t base = sm0;
        cp16(base + OFF_AHI + rA0*ROWB + qA0*16, Ahi0 + rA0*Nq + qA0*8);
        cp16(base + OFF_ALO + rA0*ROWB + qA0*16, Alo0 + rA0*Nq + qA0*8);
        cp16(base + OFF_AHI + rA1*ROWB + qA1*16, Ahi0 + rA1*Nq + qA1*8);
        cp16(base + OFF_ALO + rA1*ROWB + qA1*16, Alo0 + rA1*Nq + qA1*8);
        cp16(base + OFF_BHI + rB0*ROWB + qB0*16, Bhi0 + rB0*Nq + qB0*8);
        cp16(base + OFF_BLO + rB0*ROWB + qB0*16, Blo0 + rB0*Nq + qB0*8);
        if (tid < 128) {
            cp16(base + OFF_BHI + rB1*ROWB + qB1*16, Bhi0 + rB1*Nq + qB1*8);
            cp16(base + OFF_BLO + rB1*ROWB + qB1*16, Blo0 + rB1*Nq + qB1*8);
        }
        CP_COMMIT();
    }

    for (int c = 0; c < 16; c++) {
        if (c < 15) {
            const uint32_t base = sm0 + ((c + 1) & 1) * STGSZ;
            const int kt = (c + 1) * 32;
            cp16(base + OFF_AHI + rA0*ROWB + qA0*16, Ahi0 + rA0*Nq + kt + qA0*8);
            cp16(base + OFF_ALO + rA0*ROWB + qA0*16, Alo0 + rA0*Nq + kt + qA0*8);
            cp16(base + OFF_AHI + rA1*ROWB + qA1*16, Ahi0 + rA1*Nq + kt + qA1*8);
            cp16(base + OFF_ALO + rA1*ROWB + qA1*16, Alo0 + rA1*Nq + kt + qA1*8);
            cp16(base + OFF_BHI + rB0*ROWB + qB0*16, Bhi0 + rB0*Nq + kt + qB0*8);
            cp16(base + OFF_BLO + rB0*ROWB + qB0*16, Blo0 + rB0*Nq + kt + qB0*8);
            if (tid < 128) {
                cp16(base + OFF_BHI + rB1*ROWB + qB1*16, Bhi0 + rB1*Nq + kt + qB1*8);
                cp16(base + OFF_BLO + rB1*ROWB + qB1*16, Blo0 + rB1*Nq + kt + qB1*8);
            }
            CP_COMMIT();
            CP_WAIT1();
        } else {
            CP_WAIT0();
        }
        __syncthreads();

        const uint32_t base = sm0 + (c & 1) * STGSZ;
        const uint32_t uAhi = base + OFF_AHI;
        const uint32_t uAlo = base + OFF_ALO;
        const uint32_t uBhi = base + OFF_BHI;
        const uint32_t uBlo = base + OFF_BLO;

        #pragma unroll
        for (int ks = 0; ks < 2; ks++) {
            const uint32_t kByte = (uint32_t)(ks * 32);
            uint32_t fAhi[2][4], fAlo[2][4], fB[3][4];

            #pragma unroll
            for (int mf = 0; mf < 2; mf++)
                ldm_x4(fAhi[mf], uAhi + (wm*32 + mf*16)*ROWB + aOff + kByte);
            #pragma unroll
            for (int q = 0; q < 3; q++)
                ldm_x4(fB[q], uBhi + (wn*48 + q*16)*ROWB + bOff + kByte);
            #pragma unroll
            for (int mf = 0; mf < 2; mf++)
                #pragma unroll
                for (int q = 0; q < 3; q++) {
                    mma_bf16(acc[mf][2*q+0], fAhi[mf], &fB[q][0]);
                    mma_bf16(acc[mf][2*q+1], fAhi[mf], &fB[q][2]);
                }

            #pragma unroll
            for (int mf = 0; mf < 2; mf++)
                ldm_x4(fAlo[mf], uAlo + (wm*32 + mf*16)*ROWB + aOff + kByte);
            #pragma unroll
            for (int mf = 0; mf < 2; mf++)
                #pragma unroll
                for (int q = 0; q < 3; q++) {
                    mma_bf16(acc[mf][2*q+0], fAlo[mf], &fB[q][0]);
                    mma_bf16(acc[mf][2*q+1], fAlo[mf], &fB[q][2]);
                }

            #pragma unroll
            for (int q = 0; q < 3; q++)
                ldm_x4(fB[q], uBlo + (wn*48 + q*16)*ROWB + bOff + kByte);
            #pragma unroll
            for (int mf = 0; mf < 2; mf++)
                #pragma unroll
                for (int q = 0; q < 3; q++) {
                    mma_bf16(acc[mf][2*q+0], fAhi[mf], &fB[q][0]);
                    mma_bf16(acc[mf][2*q+1], fAhi[mf], &fB[q][2]);
                }
        }
        __syncthreads();
    }

    // Epilogue: stage fp32 tile in smem (pipeline stages are dead), then
    // coalesced split-store. Buffer 128 x 96 floats, stride 97 (conflict-free).
    float* fs = (float*)smg;
    const int quad = lane >> 2;
    const int tq   = lane & 3;
    #pragma unroll
    for (int mf = 0; mf < 2; mf++)
        #pragma unroll
        for (int nf = 0; nf < 6; nf++)
            #pragma unroll
            for (int r = 0; r < 4; r++) {
                int m = wm*32 + mf*16 + ((r >> 1) << 3) + quad;   // 0..127
                int c = wn*48 + nf*8 + tq*2 + (r & 1);            // 0..95
                fs[m*97 + c] = acc[mf][nf][r];
            }
    __syncthreads();
    for (int idx = tid; idx < 128*96; idx += 256) {
        int row = idx / 96;
        int c   = idx - row*96;
        float v = fs[row*97 + c];
        int col = bn*96 + c;
        int b = col / Pq;
        int p = col - b*Pq;
        __nv_bfloat16 hi, lo; split_bf16(v, hi, lo);
        int o = (b*Nq + bm*128 + row)*KS2 + kk*Pq + p;
        g_supHi[o] = hi;
        g_supLo[o] = lo;
    }
}

// ---------------------------------------------------------------------------
// GEMM2 via mma.sync, split-bf16 3-pass, cp.async double-buffered.
// A = sup (bf16 hi/lo, stride 208), B = Wt (bf16 hi/lo, [o][k]).
// CTA tile 128 x OUT, 13 k16 chunks. grid = 128. 256 threads. Dynamic smem.
// Epilogue: smem-staged, two coalesced passes (h/z row-major, ct o-major).
// ---------------------------------------------------------------------------
#define RB2 48

template<int OUT, bool GATE>
__global__ __launch_bounds__(256) void gemm2m_kernel(const float* __restrict__ bias,
                                                     float* __restrict__ out, int is_last) {
    constexpr int NWN = OUT/64;        // warps in N: 2 or 1
    constexpr int NWM = 8/NWN;         // warps in M: 4 or 8
    constexpr int MT  = 128/NWM;       // warp M tile: 32 or 16
    constexpr int MF  = MT/16;         // m16 frags: 2 or 1
    constexpr int OFF2_ALO = 128*RB2;              // 6144
    constexpr int OFF2_WHI = 2*128*RB2;            // 12288
    constexpr int OFF2_WLO = 2*128*RB2 + OUT*RB2;
    constexpr int STG2     = 2*128*RB2 + 2*OUT*RB2;
    constexpr int SW       = OUT + 1;              // epilogue smem stride

    extern __shared__ char smg[];

    const int bm = blockIdx.x;         // 0..127
    const int tid  = threadIdx.x;
    const int wid  = tid >> 5;
    const int lane = tid & 31;
    const int wm = wid % NWM;
    const int wn = wid / NWM;
    const uint32_t sm0 = smem_u32(smg);

    const __nv_bfloat16* WtHi = GATE ? g_WtgHi : g_WtuHi;
    const __nv_bfloat16* WtLo = GATE ? g_WtgLo : g_WtuLo;
    const __nv_bfloat16* AHi0 = g_supHi + (size_t)bm*128*KS2;
    const __nv_bfloat16* ALo0 = g_supLo + (size_t)bm*128*KS2;

    const int rA = tid >> 1, hA = tid & 1;

    float acc[MF][8][4];
    #pragma unroll
    for (int mf = 0; mf < MF; mf++)
        #pragma unroll
        for (int nf = 0; nf < 8; nf++)
            #pragma unroll
            for (int r = 0; r < 4; r++)
                acc[mf][nf][r] = bias[wn*64 + nf*8 + (lane & 3)*2 + (r & 1)];

    const uint32_t aOff = (uint32_t)((lane & 15) * RB2 + (lane >> 4) * 16);
    const uint32_t bOff = (uint32_t)(((lane & 7) + ((lane >> 4) << 3)) * RB2
                                     + (((lane >> 3) & 1) * 16));

    {   // prefetch chunk 0
        const uint32_t base = sm0;
        cp16(base + 0        + rA*RB2 + hA*16, AHi0 + rA*KS2 + hA*8);
        cp16(base + OFF2_ALO + rA*RB2 + hA*16, ALo0 + rA*KS2 + hA*8);
        if (OUT == 128) {
            cp16(base + OFF2_WHI + rA*RB2 + hA*16, WtHi + rA*KS2 + hA*8);
            cp16(base + OFF2_WLO + rA*RB2 + hA*16, WtLo + rA*KS2 + hA*8);
        } else if (tid < 128) {
            cp16(base + OFF2_WHI + rA*RB2 + hA*16, WtHi + rA*KS2 + hA*8);
            cp16(base + OFF2_WLO + rA*RB2 + hA*16, WtLo + rA*KS2 + hA*8);
        }
        CP_COMMIT();
    }

    for (int c = 0; c < 13; c++) {
        if (c < 12) {
            const uint32_t base = sm0 + ((c + 1) & 1) * STG2;
            const int kt = (c + 1) * 16;
            cp16(base + 0        + rA*RB2 + hA*16, AHi0 + rA*KS2 + kt + hA*8);
            cp16(base + OFF2_ALO + rA*RB2 + hA*16, ALo0 + rA*KS2 + kt + hA*8);
            if (OUT == 128) {
                cp16(base + OFF2_WHI + rA*RB2 + hA*16, WtHi + rA*KS2 + kt + hA*8);
                cp16(base + OFF2_WLO + rA*RB2 + hA*16, WtLo + rA*KS2 + kt + hA*8);
            } else if (tid < 128) {
                cp16(base + OFF2_WHI + rA*RB2 + hA*16, WtHi + rA*KS2 + kt + hA*8);
                cp16(base + OFF2_WLO + rA*RB2 + hA*16, WtLo + rA*KS2 + kt + hA*8);
            }
            CP_COMMIT();
            CP_WAIT1();
        } else {
            CP_WAIT0();
        }
        __syncthreads();

        const uint32_t base = sm0 + (c & 1) * STG2;
        uint32_t fAhi[MF][4], fAlo[MF][4], fW[4][4];

        #pragma unroll
        for (int mf = 0; mf < MF; mf++)
            ldm_x4(fAhi[mf], base + 0 + (wm*MT + mf*16)*RB2 + aOff);
        #pragma unroll
        for (int q = 0; q < 4; q++)
            ldm_x4(fW[q], base + OFF2_WHI + (wn*64 + q*16)*RB2 + bOff);
        #pragma unroll
        for (int mf = 0; mf < MF; mf++)
            #pragma unroll
            for (int q = 0; q < 4; q++) {
                mma_bf16(acc[mf][2*q+0], fAhi[mf], &fW[q][0]);
                mma_bf16(acc[mf][2*q+1], fAhi[mf], &fW[q][2]);
            }

        #pragma unroll
        for (int mf = 0; mf < MF; mf++)
            ldm_x4(fAlo[mf], base + OFF2_ALO + (wm*MT + mf*16)*RB2 + aOff);
        #pragma unroll
        for (int mf = 0; mf < MF; mf++)
            #pragma unroll
            for (int q = 0; q < 4; q++) {
                mma_bf16(acc[mf][2*q+0], fAlo[mf], &fW[q][0]);
                mma_bf16(acc[mf][2*q+1], fAlo[mf], &fW[q][2]);
            }

        #pragma unroll
        for (int q = 0; q < 4; q++)
            ldm_x4(fW[q], base + OFF2_WLO + (wn*64 + q*16)*RB2 + bOff);
        #pragma unroll
        for (int mf = 0; mf < MF; mf++)
            #pragma unroll
            for (int q = 0; q < 4; q++) {
                mma_bf16(acc[mf][2*q+0], fAhi[mf], &fW[q][0]);
                mma_bf16(acc[mf][2*q+1], fAhi[mf], &fW[q][2]);
            }
        __syncthreads();
    }

    // ---- Epilogue: stage acc in smem fp32 [128][SW], then coalesced passes.
    float* fs = (float*)smg;
    const int quad = lane >> 2;
    const int tq   = lane & 3;
    #pragma unroll
    for (int mf = 0; mf < MF; mf++)
        #pragma unroll
        for (int nf = 0; nf < 8; nf++)
            #pragma unroll
            for (int r = 0; r < 4; r++) {
                int rl = wm*MT + mf*16 + ((r >> 1) << 3) + quad;  // 0..127
                int o  = wn*64 + nf*8 + tq*2 + (r & 1);           // 0..OUT-1
                fs[rl*SW + o] = acc[mf][nf][r];
            }
    __syncthreads();

    if (GATE) {
        // pass1 (row-major, adjacent lanes -> adjacent o): z store + rh into smem
        for (int idx = tid; idx < 128*OUT; idx += 256) {
            int rl = idx >> 7;          // OUT = 128
            int o  = idx & 127;
            int row = bm*128 + rl;
            float zv = 1.0f / (1.0f + __expf(-fs[rl*SW + o]));
            if (o < Hq) {
                g_z[row*Hq + o] = zv;
            } else {
                fs[rl*SW + o] = zv * g_h[row*Hq + (o - Hq)];
            }
        }
        __syncthreads();
        // pass2 (o-major, adjacent lanes -> adjacent n): ct writes coalesced
        for (int idx = tid; idx < Hq*128; idx += 256) {
            int hid = idx >> 7;
            int rl  = idx & 127;
            float rh = fs[rl*SW + Hq + hid];
            __nv_bfloat16 hi, lo; split_bf16(rh, hi, lo);
            int row = bm*128 + rl;
            int b = row >> 9;
            int n = row & (Nq - 1);
            int ct = (b*Pq + Cq + hid)*Nq + n;
            g_ctHi[ct] = hi; g_ctLo[ct] = lo;
        }
    } else {
        // pass1 (row-major): GRU update; h/z/out coalesced; hnew into smem
        for (int idx = tid; idx < 128*OUT; idx += 256) {
            int rl = idx >> 6;          // OUT = 64
            int o  = idx & 63;
            int row = bm*128 + rl;
            float hc   = tanhf(fs[rl*SW + o]);
            float zv   = g_z[row*Hq + o];
            float hold = g_h[row*Hq + o];
            float hnew = (1.0f - zv)*hold + zv*hc;
            g_h[row*Hq + o] = hnew;
            if (is_last) out[row*Hq + o] = hnew;
            fs[rl*SW + o] = hnew;
        }
        __syncthreads();
        // pass2 (o-major): ct writes coalesced
        for (int idx = tid; idx < Hq*128; idx += 256) {
            int o  = idx >> 7;
            int rl = idx & 127;
            float hnew = fs[rl*SW + o];
            __nv_bfloat16 hi, lo; split_bf16(hnew, hi, lo);
            int row = bm*128 + rl;
            int b = row >> 9;
            int n = row & (Nq - 1);
            int ct = (b*Pq + Cq + o)*Nq + n;
            g_ctHi[ct] = hi; g_ctLo[ct] = lo;
        }
    }
}

// Host-side dynamic smem sizes for gemm2m
#define STG2_GATE (2*128*RB2 + 2*OUTG*RB2)          // 24576
#define STG2_UPD  (2*128*RB2 + 2*Hq*RB2)            // 18432
#define SM2_GATE  ((2*STG2_GATE) > (128*(OUTG+1)*4) ? (2*STG2_GATE) : (128*(OUTG+1)*4))
#define SM2_UPD   ((2*STG2_UPD)  > (128*(Hq+1)*4)  ? (2*STG2_UPD)  : (128*(Hq+1)*4))

// ---------------------------------------------------------------------------
// kernel_launch
// Inputs: G, x_seq, init_h, W_gate, b_gate, W_update, b_update
// ---------------------------------------------------------------------------
extern "C" void kernel_launch(void* const* d_in, const int* in_sizes, int n_in,
                              void* d_out, int out_size) {
    const float* G        = (const float*)d_in[0];
    const float* x_seq    = (const float*)d_in[1];
    const float* init_h   = (const float*)d_in[2];
    const float* W_gate   = (const float*)d_in[3];
    const float* b_gate   = (const float*)d_in[4];
    const float* W_update = (const float*)d_in[5];
    const float* b_update = (const float*)d_in[6];
    float* out = (float*)d_out;

    cudaFuncSetAttribute(gemm1_mma_kernel,
                         cudaFuncAttributeMaxDynamicSharedMemorySize, SMEM_G1);
    cudaFuncSetAttribute(gemm2m_kernel<OUTG, true>,
                         cudaFuncAttributeMaxDynamicSharedMemorySize, SM2_GATE);
    cudaFuncSetAttribute(gemm2m_kernel<Hq, false>,
                         cudaFuncAttributeMaxDynamicSharedMemorySize, SM2_UPD);

    prep_g_kernel<<<(Kq*Nq*Nq + 255)/256, 256>>>(G);
    prep_w_kernel<<<((OUTG + Hq)*KS2 + 255)/256, 256>>>(W_gate, W_update);
    init_kernel<<<(Bq*Nq*Hq + 255)/256, 256>>>(init_h);

    dim3 g1(NCOLS/96, Nq/128, Kq);   // (22, 4, 3)
    for (int t = 0; t < Tq; t++) {
        set_x_kernel<<<(Bq*Nq*Cq + 255)/256, 256>>>(x_seq, t);
        gemm1_mma_kernel<<<g1, 256, SMEM_G1>>>();
        gemm2m_kernel<OUTG, true><<<NROWS/128, 256, SM2_GATE>>>(b_gate, out, 0);
        gemm1_mma_kernel<<<g1, 256, SMEM_G1>>>();
        gemm2m_kernel<Hq, false><<<NROWS/128, 256, SM2_UPD>>>(b_update, out, t == Tq - 1);
    }
}